// round 1
// baseline (speedup 1.0000x reference)
#include <cuda_runtime.h>

// Problem constants (B=4, H=16, N=4096, D=64, M2=512, N/M2=8)
#define B_H   64
#define SEQ   4096
#define DIM   64
#define M2C   512

// Scratch (allowed: __device__ globals, no allocation)
__device__ float g_sks[B_H * DIM * M2C];   // [bh][a][m'] with m' = r*64 + d  (a-major)
__device__ float g_stv[B_H * M2C * DIM];   // [bh][m'][e]

// ---------------------------------------------------------------------------
// Kernel 1: build sketches.
//   m = d*8 + r  (d in [0,64), r in [0,8));  permuted index m' = r*64 + d.
//   SKS_P[a][m'] = (1/8) * sum_j K[r*512 + j*64 + a][d]     (scaled by 1/8)
//   STV_P[m'][e] = (1/8) * sum_j V[(d*8+r)*8 + j][e]
// Both reads and writes are fully coalesced thanks to the m' permutation
// (softmax over m is permutation-invariant; STV uses the same permutation).
// ---------------------------------------------------------------------------
__global__ __launch_bounds__(256) void sketch_kernel(const float* __restrict__ K,
                                                     const float* __restrict__ V) {
    int bh = blockIdx.x;
    int r  = blockIdx.y;                       // r in [0,8)
    const float* Kb = K + (size_t)bh * SEQ * DIM;
    const float* Vb = V + (size_t)bh * SEQ * DIM;
    float* sks = g_sks + (size_t)bh * DIM * M2C;
    float* stv = g_stv + (size_t)bh * M2C * DIM;

    for (int l = threadIdx.x; l < 64 * 64; l += 256) {
        int hi = l >> 6;       // a (for SKS) / d (for STV)
        int lo = l & 63;       // d (for SKS) / e (for STV)

        float s = 0.f;
        #pragma unroll
        for (int j = 0; j < 8; j++)
            s += Kb[(r * 512 + j * 64 + hi) * 64 + lo];
        sks[hi * 512 + r * 64 + lo] = s * 0.125f;

        float t = 0.f;
        #pragma unroll
        for (int j = 0; j < 8; j++)
            t += Vb[((hi * 8 + r) * 8 + j) * 64 + lo];
        stv[(r * 64 + hi) * 64 + lo] = t * 0.125f;
    }
}

// ---------------------------------------------------------------------------
// Kernel 2: fused  softmax(Q*SKS^T/8) @ STV + V
// Block: 256 threads (16x16), 64 query rows of one (b,h).
// Online softmax over 8 chunks of 64 sketch columns.
// Thread (ty,tx) owns a 4x4 register tile: rows 4ty.., cols 4tx..
// ---------------------------------------------------------------------------
__global__ __launch_bounds__(256) void attn_kernel(const float* __restrict__ Q,
                                                   const float* __restrict__ V,
                                                   float* __restrict__ Out) {
    extern __shared__ float sm[];
    float* Qs = sm;            // [64][64]  row-major (r, a), pre-scaled by 1/8
    float* Ks = sm + 4096;     // [64][64]  (a, mc)  SKS chunk
    float* Vs = sm + 8192;     // [64][64]  (mc, e)  STV chunk
    float* Ps = sm + 12288;    // [64][64]  (r, mc)  exp(logits)

    const int bh   = blockIdx.y;
    const int row0 = blockIdx.x * 64;
    const int tid  = threadIdx.x;
    const int tx   = tid & 15;
    const int ty   = tid >> 4;

    const float* Qb   = Q + ((size_t)bh * SEQ + row0) * DIM;
    const float* Vb   = V + ((size_t)bh * SEQ + row0) * DIM;
    float*       Ob   = Out + ((size_t)bh * SEQ + row0) * DIM;
    const float* sksb = g_sks + (size_t)bh * DIM * M2C;
    const float* stvb = g_stv + (size_t)bh * M2C * DIM;

    // Stage Q tile (scale 1/sqrt(64)=0.125 folded here)
    for (int l = tid; l < 64 * 64; l += 256)
        Qs[l] = Qb[l] * 0.125f;

    float O[4][4];
    float rmax[4], rsum[4];
    #pragma unroll
    for (int i = 0; i < 4; i++) {
        rmax[i] = -1e30f;
        rsum[i] = 0.f;
        #pragma unroll
        for (int j = 0; j < 4; j++) O[i][j] = 0.f;
    }

    for (int mc0 = 0; mc0 < M2C; mc0 += 64) {
        __syncthreads();   // prior chunk done reading Ks/Vs/Ps
        for (int l = tid; l < 64 * 64; l += 256) {
            int hi = l >> 6, lo = l & 63;
            Ks[l] = sksb[hi * 512 + mc0 + lo];       // [a][mc]
            Vs[l] = stvb[(mc0 + hi) * 64 + lo];      // [mc][e]
        }
        __syncthreads();

        // ---- GEMM1: S = Q_tile @ SKS_chunk  (k over a, vectorized x4) ----
        float S[4][4];
        #pragma unroll
        for (int i = 0; i < 4; i++)
            #pragma unroll
            for (int j = 0; j < 4; j++) S[i][j] = 0.f;

        #pragma unroll 4
        for (int a0 = 0; a0 < 64; a0 += 4) {
            float aq[4][4], bq[4][4];
            #pragma unroll
            for (int i = 0; i < 4; i++) {
                float4 t = *(const float4*)&Qs[(4 * ty + i) * 64 + a0];
                aq[i][0] = t.x; aq[i][1] = t.y; aq[i][2] = t.z; aq[i][3] = t.w;
            }
            #pragma unroll
            for (int k = 0; k < 4; k++) {
                float4 t = *(const float4*)&Ks[(a0 + k) * 64 + 4 * tx];
                bq[k][0] = t.x; bq[k][1] = t.y; bq[k][2] = t.z; bq[k][3] = t.w;
            }
            #pragma unroll
            for (int i = 0; i < 4; i++)
                #pragma unroll
                for (int k = 0; k < 4; k++)
                    #pragma unroll
                    for (int j = 0; j < 4; j++)
                        S[i][j] = fmaf(aq[i][k], bq[k][j], S[i][j]);
        }

        // ---- online softmax over this chunk ----
        #pragma unroll
        for (int i = 0; i < 4; i++) {
            float cm = fmaxf(fmaxf(S[i][0], S[i][1]), fmaxf(S[i][2], S[i][3]));
            cm = fmaxf(cm, __shfl_xor_sync(0xffffffffu, cm, 1));
            cm = fmaxf(cm, __shfl_xor_sync(0xffffffffu, cm, 2));
            cm = fmaxf(cm, __shfl_xor_sync(0xffffffffu, cm, 4));
            cm = fmaxf(cm, __shfl_xor_sync(0xffffffffu, cm, 8));
            float nm   = fmaxf(rmax[i], cm);
            float corr = __expf(rmax[i] - nm);
            rmax[i] = nm;
            float ps = 0.f;
            #pragma unroll
            for (int j = 0; j < 4; j++) {
                S[i][j] = __expf(S[i][j] - nm);
                ps += S[i][j];
            }
            rsum[i] = rsum[i] * corr + ps;
            #pragma unroll
            for (int j = 0; j < 4; j++) O[i][j] *= corr;
            *(float4*)&Ps[(4 * ty + i) * 64 + 4 * tx] =
                make_float4(S[i][0], S[i][1], S[i][2], S[i][3]);
        }
        __syncthreads();   // Ps visible to all

        // ---- GEMM2: O += P_chunk @ STV_chunk  (k over m, vectorized x4) ----
        #pragma unroll 4
        for (int m0 = 0; m0 < 64; m0 += 4) {
            float aq[4][4], bq[4][4];
            #pragma unroll
            for (int i = 0; i < 4; i++) {
                float4 t = *(const float4*)&Ps[(4 * ty + i) * 64 + m0];
                aq[i][0] = t.x; aq[i][1] = t.y; aq[i][2] = t.z; aq[i][3] = t.w;
            }
            #pragma unroll
            for (int k = 0; k < 4; k++) {
                float4 t = *(const float4*)&Vs[(m0 + k) * 64 + 4 * tx];
                bq[k][0] = t.x; bq[k][1] = t.y; bq[k][2] = t.z; bq[k][3] = t.w;
            }
            #pragma unroll
            for (int i = 0; i < 4; i++)
                #pragma unroll
                for (int k = 0; k < 4; k++)
                    #pragma unroll
                    for (int j = 0; j < 4; j++)
                        O[i][j] = fmaf(aq[i][k], bq[k][j], O[i][j]);
        }
    }

    // ---- finalize: normalize, add V residual, write ----
    #pragma unroll
    for (int i = 0; i < 4; i++) {
        float s = rsum[i];
        s += __shfl_xor_sync(0xffffffffu, s, 1);
        s += __shfl_xor_sync(0xffffffffu, s, 2);
        s += __shfl_xor_sync(0xffffffffu, s, 4);
        s += __shfl_xor_sync(0xffffffffu, s, 8);
        float inv = 1.0f / s;
        int r = 4 * ty + i;
        float4 v = *(const float4*)&Vb[r * 64 + 4 * tx];
        float4 o;
        o.x = O[i][0] * inv + v.x;
        o.y = O[i][1] * inv + v.y;
        o.z = O[i][2] * inv + v.z;
        o.w = O[i][3] * inv + v.w;
        *(float4*)&Ob[r * 64 + 4 * tx] = o;
    }
}

extern "C" void kernel_launch(void* const* d_in, const int* in_sizes, int n_in,
                              void* d_out, int out_size) {
    const float* Q = (const float*)d_in[0];
    const float* K = (const float*)d_in[1];
    const float* V = (const float*)d_in[2];
    float*       O = (float*)d_out;

    // 64KB dynamic smem needs opt-in (not a stream op; capture-safe, deterministic)
    cudaFuncSetAttribute(attn_kernel, cudaFuncAttributeMaxDynamicSharedMemorySize, 65536);

    sketch_kernel<<<dim3(B_H, 8), 256>>>(K, V);
    attn_kernel<<<dim3(SEQ / 64, B_H), 256, 65536>>>(Q, V, O);
}

// round 2
// speedup vs baseline: 2.6785x; 2.6785x over previous
#include <cuda_runtime.h>
#include <cstdint>

// Problem constants (B=4, H=16, N=4096, D=64, M2=512, N/M2=8)
#define B_H   64
#define SEQ   4096
#define DIM   64
#define M2C   512
#define LDK   68     // smem row stride (floats): (4g + t4) mod 32 hits all banks

// Scratch: tf32-rounded, 1/8 scale pre-applied.
__device__ float g_sks[B_H * M2C * DIM];   // [bh][m'][a]
__device__ float g_stv[B_H * DIM * M2C];   // [bh][e][m']

__device__ __forceinline__ uint32_t f2tf32(float f) {
    uint32_t u; asm("cvt.rna.tf32.f32 %0, %1;" : "=r"(u) : "f"(f)); return u;
}

__device__ __forceinline__ void mma_tf32(float c[4],
        uint32_t a0, uint32_t a1, uint32_t a2, uint32_t a3,
        uint32_t b0, uint32_t b1) {
    asm volatile(
        "mma.sync.aligned.m16n8k8.row.col.f32.tf32.tf32.f32 "
        "{%0,%1,%2,%3}, {%4,%5,%6,%7}, {%8,%9}, {%0,%1,%2,%3};\n"
        : "+f"(c[0]), "+f"(c[1]), "+f"(c[2]), "+f"(c[3])
        : "r"(a0), "r"(a1), "r"(a2), "r"(a3), "r"(b0), "r"(b1));
}

// ---------------------------------------------------------------------------
// Kernel 1: build sketches with m' = r*64 + d permutation (softmax-invariant,
// applied identically to SKS and STV). Transposes go through padded smem so
// both the gmem reads and writes stay coalesced.
//   SKS_P[m'=r*64+d][a] = (1/8) sum_j K[r*512 + j*64 + a][d]
//   STV_P[m'=r*64+d][e] = (1/8) sum_j V[(d*8+r)*8 + j][e]   (stored [e][m'])
// ---------------------------------------------------------------------------
__global__ __launch_bounds__(256) void sketch_kernel(const float* __restrict__ K,
                                                     const float* __restrict__ V) {
    __shared__ float acc[64 * 65];
    const int bh = blockIdx.x, r = blockIdx.y;
    const float* Kb = K + (size_t)bh * SEQ * DIM;
    const float* Vb = V + (size_t)bh * SEQ * DIM;
    float* sks = g_sks + (size_t)bh * M2C * DIM;
    float* stv = g_stv + (size_t)bh * DIM * M2C;
    const int tid = threadIdx.x;

    // SKS accumulate: acc[a][d]
    for (int l = tid; l < 4096; l += 256) {
        int a = l >> 6, d = l & 63;
        float s = 0.f;
        #pragma unroll
        for (int j = 0; j < 8; j++) s += Kb[(r * 512 + j * 64 + a) * 64 + d];
        acc[a * 65 + d] = s;
    }
    __syncthreads();
    for (int l = tid; l < 4096; l += 256) {
        int d = l >> 6, a = l & 63;
        sks[(r * 64 + d) * 64 + a] = __uint_as_float(f2tf32(acc[a * 65 + d] * 0.125f));
    }
    __syncthreads();
    // STV accumulate: acc[d][e]
    for (int l = tid; l < 4096; l += 256) {
        int d = l >> 6, e = l & 63;
        float s = 0.f;
        #pragma unroll
        for (int j = 0; j < 8; j++) s += Vb[((d * 8 + r) * 8 + j) * 64 + e];
        acc[d * 65 + e] = s;
    }
    __syncthreads();
    for (int l = tid; l < 4096; l += 256) {
        int e = l >> 6, d = l & 63;
        stv[e * 512 + r * 64 + d] = __uint_as_float(f2tf32(acc[d * 65 + e] * 0.125f));
    }
}

// ---------------------------------------------------------------------------
// Kernel 2: out = softmax(Q SKS^T / 8) @ STV + V, via tf32 mma.sync.
// Block: 256 thr (8 warps) x 128 query rows; warp owns 16 rows.
// Loop over 8 chunks of 64 sketch columns. No max-subtraction (|logit|<~2.5).
// P round-trips through warp-private smem (no barrier: same-warp STS->LDS).
// ---------------------------------------------------------------------------
__global__ __launch_bounds__(256, 2) void attn_kernel(const float* __restrict__ Q,
                                                      const float* __restrict__ V,
                                                      float* __restrict__ Out) {
    extern __shared__ float sm[];
    float* KsT = sm;                  // [mc 64][LDK] : (mc, a)
    float* VsT = sm + 64 * LDK;       // [e 64][LDK]  : (e, m)
    float* Ps  = sm + 2 * 64 * LDK;   // 8 warps x [16][LDK]

    const int tid  = threadIdx.x;
    const int lane = tid & 31, warp = tid >> 5;
    const int g = lane >> 2, t4 = lane & 3;
    const int bh   = blockIdx.y;
    const int wrow = blockIdx.x * 128 + warp * 16;

    const float* Qb   = Q + (size_t)bh * SEQ * DIM;
    const float* sksb = g_sks + (size_t)bh * M2C * DIM;
    const float* stvb = g_stv + (size_t)bh * DIM * M2C;
    float* Pw = Ps + warp * 16 * LDK;

    // Persistent Q fragments (scale 1/8 + tf32 round folded in)
    uint32_t Qa[8][4];
    {
        const float* q0 = Qb + (size_t)(wrow + g) * DIM;
        const float* q1 = Qb + (size_t)(wrow + g + 8) * DIM;
        #pragma unroll
        for (int kk = 0; kk < 8; kk++) {
            Qa[kk][0] = f2tf32(q0[kk * 8 + t4] * 0.125f);
            Qa[kk][1] = f2tf32(q1[kk * 8 + t4] * 0.125f);
            Qa[kk][2] = f2tf32(q0[kk * 8 + t4 + 4] * 0.125f);
            Qa[kk][3] = f2tf32(q1[kk * 8 + t4 + 4] * 0.125f);
        }
    }

    float O[8][4];
    #pragma unroll
    for (int j = 0; j < 8; j++) { O[j][0] = O[j][1] = O[j][2] = O[j][3] = 0.f; }
    float sum_lo = 0.f, sum_hi = 0.f;

    for (int mc0 = 0; mc0 < M2C; mc0 += 64) {
        __syncthreads();   // previous chunk finished reading KsT/VsT
        for (int l = tid; l < 64 * 16; l += 256) {          // float4 staging
            int row = l >> 4, c4 = (l & 15) * 4;
            *(float4*)&KsT[row * LDK + c4] = *(const float4*)&sksb[(mc0 + row) * 64 + c4];
            *(float4*)&VsT[row * LDK + c4] = *(const float4*)&stvb[row * 512 + mc0 + c4];
        }
        __syncthreads();

        // GEMM1: S[16 x 64] = Q_tile @ SKS_chunk^T
        float S[8][4];
        #pragma unroll
        for (int j = 0; j < 8; j++) S[j][0] = S[j][1] = S[j][2] = S[j][3] = 0.f;
        #pragma unroll
        for (int kk = 0; kk < 8; kk++) {
            #pragma unroll
            for (int j = 0; j < 8; j++) {
                uint32_t b0 = __float_as_uint(KsT[(j * 8 + g) * LDK + kk * 8 + t4]);
                uint32_t b1 = __float_as_uint(KsT[(j * 8 + g) * LDK + kk * 8 + t4 + 4]);
                mma_tf32(S[j], Qa[kk][0], Qa[kk][1], Qa[kk][2], Qa[kk][3], b0, b1);
            }
        }

        // exp + row sums + store P (tf32) to warp-private smem
        #pragma unroll
        for (int j = 0; j < 8; j++) {
            float p0 = __expf(S[j][0]), p1 = __expf(S[j][1]);
            float p2 = __expf(S[j][2]), p3 = __expf(S[j][3]);
            sum_lo += p0 + p1;
            sum_hi += p2 + p3;
            *(uint2*)&Pw[g * LDK + j * 8 + 2 * t4]       = make_uint2(f2tf32(p0), f2tf32(p1));
            *(uint2*)&Pw[(g + 8) * LDK + j * 8 + 2 * t4] = make_uint2(f2tf32(p2), f2tf32(p3));
        }

        // GEMM2: O += P_chunk @ STV_chunk
        #pragma unroll
        for (int kk = 0; kk < 8; kk++) {
            uint32_t a0 = __float_as_uint(Pw[g * LDK + kk * 8 + t4]);
            uint32_t a1 = __float_as_uint(Pw[(g + 8) * LDK + kk * 8 + t4]);
            uint32_t a2 = __float_as_uint(Pw[g * LDK + kk * 8 + t4 + 4]);
            uint32_t a3 = __float_as_uint(Pw[(g + 8) * LDK + kk * 8 + t4 + 4]);
            #pragma unroll
            for (int j = 0; j < 8; j++) {
                uint32_t b0 = __float_as_uint(VsT[(j * 8 + g) * LDK + kk * 8 + t4]);
                uint32_t b1 = __float_as_uint(VsT[(j * 8 + g) * LDK + kk * 8 + t4 + 4]);
                mma_tf32(O[j], a0, a1, a2, a3, b0, b1);
            }
        }
    }

    // Reduce row sums within each quad (lanes 4g..4g+3 share row g)
    sum_lo += __shfl_xor_sync(0xffffffffu, sum_lo, 1);
    sum_lo += __shfl_xor_sync(0xffffffffu, sum_lo, 2);
    sum_hi += __shfl_xor_sync(0xffffffffu, sum_hi, 1);
    sum_hi += __shfl_xor_sync(0xffffffffu, sum_hi, 2);
    const float inv_lo = 1.0f / sum_lo, inv_hi = 1.0f / sum_hi;

    const float* Vb = V + (size_t)bh * SEQ * DIM;
    float* Ob = Out + (size_t)bh * SEQ * DIM;
    const int r_lo = wrow + g, r_hi = wrow + g + 8;
    #pragma unroll
    for (int j = 0; j < 8; j++) {
        int c = j * 8 + 2 * t4;
        float2 v0 = *(const float2*)&Vb[(size_t)r_lo * DIM + c];
        float2 v1 = *(const float2*)&Vb[(size_t)r_hi * DIM + c];
        float2 o0 = make_float2(O[j][0] * inv_lo + v0.x, O[j][1] * inv_lo + v0.y);
        float2 o1 = make_float2(O[j][2] * inv_hi + v1.x, O[j][3] * inv_hi + v1.y);
        *(float2*)&Ob[(size_t)r_lo * DIM + c] = o0;
        *(float2*)&Ob[(size_t)r_hi * DIM + c] = o1;
    }
}

extern "C" void kernel_launch(void* const* d_in, const int* in_sizes, int n_in,
                              void* d_out, int out_size) {
    const float* Q = (const float*)d_in[0];
    const float* K = (const float*)d_in[1];
    const float* V = (const float*)d_in[2];
    float*       O = (float*)d_out;

    const int smem = (2 * 64 * LDK + 8 * 16 * LDK) * sizeof(float);  // 69632 B
    cudaFuncSetAttribute(attn_kernel, cudaFuncAttributeMaxDynamicSharedMemorySize, smem);

    sketch_kernel<<<dim3(B_H, 8), 256>>>(K, V);
    attn_kernel<<<dim3(SEQ / 128, B_H), 256, smem>>>(Q, V, O);
}

// round 3
// speedup vs baseline: 2.8681x; 1.0708x over previous
#include <cuda_runtime.h>
#include <cstdint>

// Problem constants (B=4, H=16, N=4096, D=64, M2=512, N/M2=8)
#define B_H   64
#define SEQ   4096
#define DIM   64
#define M2C   512
#define LDS_S 72     // smem row stride in floats (72 mod 32 == 8 -> conflict-free frag loads)

// Scratch: tf32-rounded, 1/8 scale pre-applied, k-groups pair-interleaved:
// within each group of 8 along the contraction dim, logical k is stored at
// physical 2*(k&3) + ((k>>2)&1), so (k, k+4) are adjacent -> LDS.64 fragments.
__device__ float g_sks[B_H * M2C * DIM];   // [bh][m'][a~]   (a interleaved)
__device__ float g_stv[B_H * DIM * M2C];   // [bh][e][m'~]   (m' interleaved)

__device__ __forceinline__ uint32_t f2tf32(float f) {
    uint32_t u; asm("cvt.rna.tf32.f32 %0, %1;" : "=r"(u) : "f"(f)); return u;
}
__device__ __forceinline__ int ileave(int k) {   // interleave within 8-group
    return (k & ~7) + 2 * (k & 3) + ((k >> 2) & 1);
}

__device__ __forceinline__ void mma_tf32(float c[4],
        uint32_t a0, uint32_t a1, uint32_t a2, uint32_t a3,
        uint32_t b0, uint32_t b1) {
    asm volatile(
        "mma.sync.aligned.m16n8k8.row.col.f32.tf32.tf32.f32 "
        "{%0,%1,%2,%3}, {%4,%5,%6,%7}, {%8,%9}, {%0,%1,%2,%3};\n"
        : "+f"(c[0]), "+f"(c[1]), "+f"(c[2]), "+f"(c[3])
        : "r"(a0), "r"(a1), "r"(a2), "r"(a3), "r"(b0), "r"(b1));
}

// ---------------------------------------------------------------------------
// Kernel 1: build sketches, m' = r*64 + d permutation (softmax-invariant, same
// permutation on SKS and STV so the result is exact). Writes interleaved.
//   SKS_P[m'][a~] = (1/8) sum_j K[r*512 + j*64 + a][d]
//   STV_P[e][m'~] = (1/8) sum_j V[(d*8+r)*8 + j][e]
// ---------------------------------------------------------------------------
__global__ __launch_bounds__(256) void sketch_kernel(const float* __restrict__ K,
                                                     const float* __restrict__ V) {
    __shared__ float acc[64 * 65];
    const int bh = blockIdx.x, r = blockIdx.y;
    const float* Kb = K + (size_t)bh * SEQ * DIM;
    const float* Vb = V + (size_t)bh * SEQ * DIM;
    float* sks = g_sks + (size_t)bh * M2C * DIM;
    float* stv = g_stv + (size_t)bh * DIM * M2C;
    const int tid = threadIdx.x;

    for (int l = tid; l < 4096; l += 256) {            // acc[a][d]
        int a = l >> 6, d = l & 63;
        float s = 0.f;
        #pragma unroll
        for (int j = 0; j < 8; j++) s += Kb[(r * 512 + j * 64 + a) * 64 + d];
        acc[a * 65 + d] = s;
    }
    __syncthreads();
    for (int l = tid; l < 4096; l += 256) {
        int d = l >> 6, a = l & 63;
        sks[(r * 64 + d) * 64 + ileave(a)] = __uint_as_float(f2tf32(acc[a * 65 + d] * 0.125f));
    }
    __syncthreads();
    for (int l = tid; l < 4096; l += 256) {            // acc[d][e]
        int d = l >> 6, e = l & 63;
        float s = 0.f;
        #pragma unroll
        for (int j = 0; j < 8; j++) s += Vb[((d * 8 + r) * 8 + j) * 64 + e];
        acc[d * 65 + e] = s;
    }
    __syncthreads();
    for (int l = tid; l < 4096; l += 256) {
        int e = l >> 6, d = l & 63;
        stv[e * 512 + r * 64 + ileave(d)] = __uint_as_float(f2tf32(acc[d * 65 + e] * 0.125f));
    }
}

// ---------------------------------------------------------------------------
// Kernel 2: out = softmax(Q SKS^T / 8) @ STV + V  (tf32 mma.sync)
// 128 threads (4 warps), warp owns 32 query rows (two m16 tiles sharing every
// B fragment). 8 chunks of 64 sketch columns. All fragment LDS are 64-bit and
// conflict-free; P goes through warp-private smem (no barrier needed).
// exp via MUFU.EX2 with log2(e)/8 folded into Q.
// ---------------------------------------------------------------------------
__global__ __launch_bounds__(128, 2) void attn_kernel(const float* __restrict__ Q,
                                                      const float* __restrict__ V,
                                                      float* __restrict__ Out) {
    extern __shared__ float sm[];
    float* KsT = sm;                       // [mc 64][LDS_S] (n=mc, k=a~)
    float* VsT = sm + 64 * LDS_S;          // [e 64][LDS_S]  (n=e, k=m'~)
    float* Ps  = sm + 2 * 64 * LDS_S;      // 4 warps x [32][LDS_S]

    const int tid  = threadIdx.x;
    const int lane = tid & 31, warp = tid >> 5;
    const int g = lane >> 2, t4 = lane & 3;
    const int xr = (g & 4) ? 2 : 0;                     // P row-swizzle
    const int ip0 = (t4 & 1) * 4 + (t4 >> 1);           // ileave(2*t4)
    const int bh   = blockIdx.y;
    const int wrow = blockIdx.x * 128 + warp * 32;

    const float* Qb   = Q + (size_t)bh * SEQ * DIM;
    const float* sksb = g_sks + (size_t)bh * M2C * DIM;
    const float* stvb = g_stv + (size_t)bh * DIM * M2C;
    float* Pw = Ps + warp * 32 * LDS_S;

    // Persistent Q fragments for both 16-row tiles (scale log2e/8 + tf32 round)
    const float qs = 0.125f * 1.4426950408889634f;
    uint32_t Qa[8][8];
    #pragma unroll
    for (int tt = 0; tt < 2; tt++) {
        const float* q0 = Qb + (size_t)(wrow + tt * 16 + g) * DIM;
        const float* q1 = Qb + (size_t)(wrow + tt * 16 + g + 8) * DIM;
        #pragma unroll
        for (int kk = 0; kk < 8; kk++) {
            Qa[kk][tt * 4 + 0] = f2tf32(q0[kk * 8 + t4] * qs);
            Qa[kk][tt * 4 + 1] = f2tf32(q1[kk * 8 + t4] * qs);
            Qa[kk][tt * 4 + 2] = f2tf32(q0[kk * 8 + t4 + 4] * qs);
            Qa[kk][tt * 4 + 3] = f2tf32(q1[kk * 8 + t4 + 4] * qs);
        }
    }

    float O0[8][4], O1[8][4];
    #pragma unroll
    for (int j = 0; j < 8; j++)
        #pragma unroll
        for (int c = 0; c < 4; c++) { O0[j][c] = 0.f; O1[j][c] = 0.f; }
    float sum0 = 0.f, sum1 = 0.f, sum2 = 0.f, sum3 = 0.f;

    for (int mc0 = 0; mc0 < M2C; mc0 += 64) {
        __syncthreads();   // all warps done reading KsT/VsT of previous chunk
        for (int l = tid; l < 1024; l += 128) {
            int row = l >> 4, c4 = (l & 15) * 4;
            *(float4*)&KsT[row * LDS_S + c4] = *(const float4*)&sksb[(mc0 + row) * 64 + c4];
            *(float4*)&VsT[row * LDS_S + c4] = *(const float4*)&stvb[row * 512 + mc0 + c4];
        }
        __syncthreads();

        // ---- GEMM1 + exp + P store, j outer (live S = 8 regs) ----
        #pragma unroll
        for (int j = 0; j < 8; j++) {
            float S0[4] = {0.f, 0.f, 0.f, 0.f}, S1[4] = {0.f, 0.f, 0.f, 0.f};
            #pragma unroll
            for (int kk = 0; kk < 8; kk++) {
                float2 b = *(const float2*)&KsT[(j * 8 + g) * LDS_S + kk * 8 + 2 * t4];
                uint32_t b0 = __float_as_uint(b.x), b1 = __float_as_uint(b.y);
                mma_tf32(S0, Qa[kk][0], Qa[kk][1], Qa[kk][2], Qa[kk][3], b0, b1);
                mma_tf32(S1, Qa[kk][4], Qa[kk][5], Qa[kk][6], Qa[kk][7], b0, b1);
            }
            float p00 = exp2f(S0[0]), p01 = exp2f(S0[1]);
            float p02 = exp2f(S0[2]), p03 = exp2f(S0[3]);
            float p10 = exp2f(S1[0]), p11 = exp2f(S1[1]);
            float p12 = exp2f(S1[2]), p13 = exp2f(S1[3]);
            sum0 += p00 + p01;  sum1 += p02 + p03;
            sum2 += p10 + p11;  sum3 += p12 + p13;
            int ca = j * 8 + (ip0 ^ xr);
            int cb = j * 8 + ((ip0 + 2) ^ xr);
            Pw[(g     ) * LDS_S + ca] = __uint_as_float(f2tf32(p00));
            Pw[(g     ) * LDS_S + cb] = __uint_as_float(f2tf32(p01));
            Pw[(g +  8) * LDS_S + ca] = __uint_as_float(f2tf32(p02));
            Pw[(g +  8) * LDS_S + cb] = __uint_as_float(f2tf32(p03));
            Pw[(g + 16) * LDS_S + ca] = __uint_as_float(f2tf32(p10));
            Pw[(g + 16) * LDS_S + cb] = __uint_as_float(f2tf32(p11));
            Pw[(g + 24) * LDS_S + ca] = __uint_as_float(f2tf32(p12));
            Pw[(g + 24) * LDS_S + cb] = __uint_as_float(f2tf32(p13));
        }
        // Pw is warp-private; same-warp STS->LDS needs no barrier.

        // ---- GEMM2: O += P @ STV, kk outer (A loaded once per kk) ----
        #pragma unroll
        for (int kk = 0; kk < 8; kk++) {
            int kc = kk * 8 + (2 * t4 ^ xr);
            float2 aA = *(const float2*)&Pw[(g     ) * LDS_S + kc];
            float2 aB = *(const float2*)&Pw[(g +  8) * LDS_S + kc];
            float2 aC = *(const float2*)&Pw[(g + 16) * LDS_S + kc];
            float2 aD = *(const float2*)&Pw[(g + 24) * LDS_S + kc];
            uint32_t a0 = __float_as_uint(aA.x), a1 = __float_as_uint(aB.x);
            uint32_t a2 = __float_as_uint(aA.y), a3 = __float_as_uint(aB.y);
            uint32_t a4 = __float_as_uint(aC.x), a5 = __float_as_uint(aD.x);
            uint32_t a6 = __float_as_uint(aC.y), a7 = __float_as_uint(aD.y);
            #pragma unroll
            for (int j = 0; j < 8; j++) {
                float2 b = *(const float2*)&VsT[(j * 8 + g) * LDS_S + kk * 8 + 2 * t4];
                uint32_t b0 = __float_as_uint(b.x), b1 = __float_as_uint(b.y);
                mma_tf32(O0[j], a0, a1, a2, a3, b0, b1);
                mma_tf32(O1[j], a4, a5, a6, a7, b0, b1);
            }
        }
    }

    // quad-reduce row sums (lanes 4g..4g+3 share rows)
    sum0 += __shfl_xor_sync(0xffffffffu, sum0, 1);
    sum0 += __shfl_xor_sync(0xffffffffu, sum0, 2);
    sum1 += __shfl_xor_sync(0xffffffffu, sum1, 1);
    sum1 += __shfl_xor_sync(0xffffffffu, sum1, 2);
    sum2 += __shfl_xor_sync(0xffffffffu, sum2, 1);
    sum2 += __shfl_xor_sync(0xffffffffu, sum2, 2);
    sum3 += __shfl_xor_sync(0xffffffffu, sum3, 1);
    sum3 += __shfl_xor_sync(0xffffffffu, sum3, 2);
    const float i0 = 1.f / sum0, i1 = 1.f / sum1, i2 = 1.f / sum2, i3 = 1.f / sum3;

    const float* Vb = V + (size_t)bh * SEQ * DIM;
    float* Ob = Out + (size_t)bh * SEQ * DIM;
    const size_t r0 = wrow + g, r1 = r0 + 8, r2 = r0 + 16, r3 = r0 + 24;
    #pragma unroll
    for (int j = 0; j < 8; j++) {
        int c = j * 8 + 2 * t4;
        float2 v0 = *(const float2*)&Vb[r0 * DIM + c];
        float2 v1 = *(const float2*)&Vb[r1 * DIM + c];
        float2 v2 = *(const float2*)&Vb[r2 * DIM + c];
        float2 v3 = *(const float2*)&Vb[r3 * DIM + c];
        *(float2*)&Ob[r0 * DIM + c] = make_float2(O0[j][0] * i0 + v0.x, O0[j][1] * i0 + v0.y);
        *(float2*)&Ob[r1 * DIM + c] = make_float2(O0[j][2] * i1 + v1.x, O0[j][3] * i1 + v1.y);
        *(float2*)&Ob[r2 * DIM + c] = make_float2(O1[j][0] * i2 + v2.x, O1[j][1] * i2 + v2.y);
        *(float2*)&Ob[r3 * DIM + c] = make_float2(O1[j][2] * i3 + v3.x, O1[j][3] * i3 + v3.y);
    }
}

extern "C" void kernel_launch(void* const* d_in, const int* in_sizes, int n_in,
                              void* d_out, int out_size) {
    const float* Q = (const float*)d_in[0];
    const float* K = (const float*)d_in[1];
    const float* V = (const float*)d_in[2];
    float*       O = (float*)d_out;

    const int smem = (2 * 64 * LDS_S + 4 * 32 * LDS_S) * sizeof(float);  // 73728 B
    cudaFuncSetAttribute(attn_kernel, cudaFuncAttributeMaxDynamicSharedMemorySize, smem);

    sketch_kernel<<<dim3(B_H, 8), 256>>>(K, V);
    attn_kernel<<<dim3(SEQ / 128, B_H), 128, smem>>>(Q, V, O);
}

// round 4
// speedup vs baseline: 4.1265x; 1.4388x over previous
#include <cuda_runtime.h>
#include <cuda_bf16.h>
#include <cstdint>

// Problem constants (B=4, H=16, N=4096, D=64, M2=512, N/M2=8)
#define B_H   64
#define SEQ   4096
#define DIM   64
#define M2C   512
#define SROW  80    // smem row stride in bf16 elems; 160B = 32B mod 128 -> conflict-free LDS.64

// Scratch sketches in bf16, 1/8 scale pre-applied, contraction dim pair-interleaved:
// within each 16-elem k-group, pair p=(k>>1)&7 sits at phys pair 2*(p&3)+(p>>2),
// so a thread's (k=2t4, k=2t4+8) fragment pairs are adjacent -> one LDS.64.
__device__ __nv_bfloat16 g_sks[B_H * M2C * DIM];   // [bh][m'][a~]
__device__ __nv_bfloat16 g_stv[B_H * DIM * M2C];   // [bh][e][m'~]

__device__ __forceinline__ int ileave16(int k) {
    int p = (k >> 1) & 7;
    return (k & ~15) + ((2 * (p & 3) + (p >> 2)) << 1) + (k & 1);
}
__device__ __forceinline__ float ex2(float x) {
    float y; asm("ex2.approx.f32 %0, %1;" : "=f"(y) : "f"(x)); return y;
}
__device__ __forceinline__ uint32_t pack_bf2(float lo, float hi) {
    __nv_bfloat162 h = __floats2bfloat162_rn(lo, hi);
    return *(uint32_t*)&h;
}
__device__ __forceinline__ void mma_bf16(float c[4],
        uint32_t a0, uint32_t a1, uint32_t a2, uint32_t a3,
        uint32_t b0, uint32_t b1) {
    asm volatile(
        "mma.sync.aligned.m16n8k16.row.col.f32.bf16.bf16.f32 "
        "{%0,%1,%2,%3}, {%4,%5,%6,%7}, {%8,%9}, {%0,%1,%2,%3};\n"
        : "+f"(c[0]), "+f"(c[1]), "+f"(c[2]), "+f"(c[3])
        : "r"(a0), "r"(a1), "r"(a2), "r"(a3), "r"(b0), "r"(b1));
}

// ---------------------------------------------------------------------------
// Kernel 1: build sketches, m' = r*64 + d permutation (softmax-invariant; the
// same permutation is applied to SKS and STV so the result is exact).
//   SKS_P[m'][a~] = (1/8) sum_j K[r*512 + j*64 + a][d]
//   STV_P[e][m'~] = (1/8) sum_j V[(d*8+r)*8 + j][e]
// ---------------------------------------------------------------------------
__global__ __launch_bounds__(256) void sketch_kernel(const float* __restrict__ K,
                                                     const float* __restrict__ V) {
    __shared__ float acc[64 * 65];
    const int bh = blockIdx.x, r = blockIdx.y;
    const float* Kb = K + (size_t)bh * SEQ * DIM;
    const float* Vb = V + (size_t)bh * SEQ * DIM;
    __nv_bfloat16* sks = g_sks + (size_t)bh * M2C * DIM;
    __nv_bfloat16* stv = g_stv + (size_t)bh * DIM * M2C;
    const int tid = threadIdx.x;

    for (int l = tid; l < 4096; l += 256) {            // acc[a][d]
        int a = l >> 6, d = l & 63;
        float s = 0.f;
        #pragma unroll
        for (int j = 0; j < 8; j++) s += Kb[(r * 512 + j * 64 + a) * 64 + d];
        acc[a * 65 + d] = s;
    }
    __syncthreads();
    for (int l = tid; l < 4096; l += 256) {
        int d = l >> 6, a = l & 63;
        sks[(r * 64 + d) * 64 + ileave16(a)] = __float2bfloat16_rn(acc[a * 65 + d] * 0.125f);
    }
    __syncthreads();
    for (int l = tid; l < 4096; l += 256) {            // acc[d][e]
        int d = l >> 6, e = l & 63;
        float s = 0.f;
        #pragma unroll
        for (int j = 0; j < 8; j++) s += Vb[((d * 8 + r) * 8 + j) * 64 + e];
        acc[d * 65 + e] = s;
    }
    __syncthreads();
    for (int l = tid; l < 4096; l += 256) {
        int e = l >> 6, d = l & 63;
        stv[e * 512 + r * 64 + ileave16(d)] = __float2bfloat16_rn(acc[d * 65 + e] * 0.125f);
    }
}

// ---------------------------------------------------------------------------
// Kernel 2: out = softmax(Q SKS^T / 8) @ STV + V  via bf16 m16n8k16 mma.sync.
// 128 threads (4 warps); warp owns 32 query rows (two m16 tiles sharing every
// B fragment). 8 chunks of 64 sketch columns. GEMM1 runs j in pairs -> 4
// independent accumulator chains of depth 4. exp via MUFU.EX2 (log2e/8 folded
// into Q). P round-trips through warp-private smem as bf16 (no barrier).
// ---------------------------------------------------------------------------
__global__ __launch_bounds__(128, 3) void attn_kernel(const float* __restrict__ Q,
                                                      const float* __restrict__ V,
                                                      float* __restrict__ Out) {
    extern __shared__ __align__(16) char smb[];
    __nv_bfloat16* Ks = (__nv_bfloat16*)smb;                 // [mc 64][SROW]
    __nv_bfloat16* Vs = Ks + 64 * SROW;                      // [e  64][SROW]
    __nv_bfloat16* Ps = Vs + 64 * SROW;                      // 4 warps x [32][SROW]

    const int tid  = threadIdx.x;
    const int lane = tid & 31, warp = tid >> 5;
    const int g = lane >> 2, t4 = lane & 3;
    const int bh   = blockIdx.y;
    const int wrow = blockIdx.x * 128 + warp * 32;

    const float* Qb = Q + (size_t)bh * SEQ * DIM;
    const __nv_bfloat16* sksb = g_sks + (size_t)bh * M2C * DIM;
    const __nv_bfloat16* stvb = g_stv + (size_t)bh * DIM * M2C;
    __nv_bfloat16* Pw = Ps + warp * 32 * SROW;

    // Persistent Q fragments (both 16-row tiles); scale 0.125*log2(e) folded.
    const float qs = 0.125f * 1.4426950408889634f;
    uint32_t Qa[4][8];
    #pragma unroll
    for (int tt = 0; tt < 2; tt++) {
        const float* q0 = Qb + (size_t)(wrow + tt * 16 + g) * DIM;
        const float* q1 = Qb + (size_t)(wrow + tt * 16 + g + 8) * DIM;
        #pragma unroll
        for (int kk = 0; kk < 4; kk++) {
            float2 x0 = *(const float2*)&q0[kk * 16 + 2 * t4];
            float2 x1 = *(const float2*)&q1[kk * 16 + 2 * t4];
            float2 x2 = *(const float2*)&q0[kk * 16 + 2 * t4 + 8];
            float2 x3 = *(const float2*)&q1[kk * 16 + 2 * t4 + 8];
            Qa[kk][tt * 4 + 0] = pack_bf2(x0.x * qs, x0.y * qs);
            Qa[kk][tt * 4 + 1] = pack_bf2(x1.x * qs, x1.y * qs);
            Qa[kk][tt * 4 + 2] = pack_bf2(x2.x * qs, x2.y * qs);
            Qa[kk][tt * 4 + 3] = pack_bf2(x3.x * qs, x3.y * qs);
        }
    }

    float O0[8][4], O1[8][4];
    #pragma unroll
    for (int j = 0; j < 8; j++)
        #pragma unroll
        for (int c = 0; c < 4; c++) { O0[j][c] = 0.f; O1[j][c] = 0.f; }
    float sum0 = 0.f, sum1 = 0.f, sum2 = 0.f, sum3 = 0.f;

    for (int mc0 = 0; mc0 < M2C; mc0 += 64) {
        __syncthreads();   // all warps done reading previous chunk tiles
        for (int l = tid; l < 512; l += 128) {           // 16B copies
            int row = l >> 3, seg = (l & 7) * 8;
            *(uint4*)&Ks[row * SROW + seg] = *(const uint4*)&sksb[(mc0 + row) * 64 + seg];
            *(uint4*)&Vs[row * SROW + seg] = *(const uint4*)&stvb[row * 512 + mc0 + seg];
        }
        __syncthreads();

        // ---- GEMM1 (j pairs) + exp + P store ----
        #pragma unroll
        for (int jj = 0; jj < 4; jj++) {
            const int j0 = 2 * jj, j1 = 2 * jj + 1;
            float Sa[4] = {0,0,0,0}, Sb[4] = {0,0,0,0};   // tile0/tile1, col j0
            float Sc[4] = {0,0,0,0}, Sd[4] = {0,0,0,0};   // tile0/tile1, col j1
            #pragma unroll
            for (int kk = 0; kk < 4; kk++) {
                uint2 Bx = *(const uint2*)&Ks[(j0 * 8 + g) * SROW + kk * 16 + 4 * t4];
                uint2 By = *(const uint2*)&Ks[(j1 * 8 + g) * SROW + kk * 16 + 4 * t4];
                mma_bf16(Sa, Qa[kk][0], Qa[kk][1], Qa[kk][2], Qa[kk][3], Bx.x, Bx.y);
                mma_bf16(Sb, Qa[kk][4], Qa[kk][5], Qa[kk][6], Qa[kk][7], Bx.x, Bx.y);
                mma_bf16(Sc, Qa[kk][0], Qa[kk][1], Qa[kk][2], Qa[kk][3], By.x, By.y);
                mma_bf16(Sd, Qa[kk][4], Qa[kk][5], Qa[kk][6], Qa[kk][7], By.x, By.y);
            }
            #pragma unroll
            for (int h = 0; h < 2; h++) {                 // h=0 -> j0, h=1 -> j1
                const int j = h ? j1 : j0;
                float* S0 = h ? Sc : Sa;
                float* S1 = h ? Sd : Sb;
                float p00 = ex2(S0[0]), p01 = ex2(S0[1]);
                float p02 = ex2(S0[2]), p03 = ex2(S0[3]);
                float p10 = ex2(S1[0]), p11 = ex2(S1[1]);
                float p12 = ex2(S1[2]), p13 = ex2(S1[3]);
                sum0 += p00 + p01;  sum1 += p02 + p03;
                sum2 += p10 + p11;  sum3 += p12 + p13;
                // k = j*8 + 2t4 -> phys word (j>>1)*8 + 2t4 + (j&1), elems x2
                const int co = (j >> 1) * 16 + (2 * t4 + (j & 1)) * 2;
                *(uint32_t*)&Pw[(g     ) * SROW + co] = pack_bf2(p00, p01);
                *(uint32_t*)&Pw[(g +  8) * SROW + co] = pack_bf2(p02, p03);
                *(uint32_t*)&Pw[(g + 16) * SROW + co] = pack_bf2(p10, p11);
                *(uint32_t*)&Pw[(g + 24) * SROW + co] = pack_bf2(p12, p13);
            }
        }
        // Pw is warp-private; same-warp STS->LDS needs no barrier.

        // ---- GEMM2: O += P @ STV ----
        #pragma unroll
        for (int kk = 0; kk < 4; kk++) {
            uint2 uA = *(const uint2*)&Pw[(g     ) * SROW + kk * 16 + 4 * t4];
            uint2 uB = *(const uint2*)&Pw[(g +  8) * SROW + kk * 16 + 4 * t4];
            uint2 uC = *(const uint2*)&Pw[(g + 16) * SROW + kk * 16 + 4 * t4];
            uint2 uD = *(const uint2*)&Pw[(g + 24) * SROW + kk * 16 + 4 * t4];
            #pragma unroll
            for (int j = 0; j < 8; j++) {
                uint2 Bv = *(const uint2*)&Vs[(j * 8 + g) * SROW + kk * 16 + 4 * t4];
                mma_bf16(O0[j], uA.x, uB.x, uA.y, uB.y, Bv.x, Bv.y);
                mma_bf16(O1[j], uC.x, uD.x, uC.y, uD.y, Bv.x, Bv.y);
            }
        }
    }

    // quad-reduce row sums (lanes 4g..4g+3 share rows)
    sum0 += __shfl_xor_sync(0xffffffffu, sum0, 1);
    sum0 += __shfl_xor_sync(0xffffffffu, sum0, 2);
    sum1 += __shfl_xor_sync(0xffffffffu, sum1, 1);
    sum1 += __shfl_xor_sync(0xffffffffu, sum1, 2);
    sum2 += __shfl_xor_sync(0xffffffffu, sum2, 1);
    sum2 += __shfl_xor_sync(0xffffffffu, sum2, 2);
    sum3 += __shfl_xor_sync(0xffffffffu, sum3, 1);
    sum3 += __shfl_xor_sync(0xffffffffu, sum3, 2);
    const float i0 = 1.f / sum0, i1 = 1.f / sum1, i2 = 1.f / sum2, i3 = 1.f / sum3;

    const float* Vb = V + (size_t)bh * SEQ * DIM;
    float* Ob = Out + (size_t)bh * SEQ * DIM;
    const size_t r0 = wrow + g, r1 = r0 + 8, r2 = r0 + 16, r3 = r0 + 24;
    #pragma unroll
    for (int j = 0; j < 8; j++) {
        int c = j * 8 + 2 * t4;
        float2 v0 = *(const float2*)&Vb[r0 * DIM + c];
        float2 v1 = *(const float2*)&Vb[r1 * DIM + c];
        float2 v2 = *(const float2*)&Vb[r2 * DIM + c];
        float2 v3 = *(const float2*)&Vb[r3 * DIM + c];
        *(float2*)&Ob[r0 * DIM + c] = make_float2(O0[j][0] * i0 + v0.x, O0[j][1] * i0 + v0.y);
        *(float2*)&Ob[r1 * DIM + c] = make_float2(O0[j][2] * i1 + v1.x, O0[j][3] * i1 + v1.y);
        *(float2*)&Ob[r2 * DIM + c] = make_float2(O1[j][0] * i2 + v2.x, O1[j][1] * i2 + v2.y);
        *(float2*)&Ob[r3 * DIM + c] = make_float2(O1[j][2] * i3 + v3.x, O1[j][3] * i3 + v3.y);
    }
}

extern "C" void kernel_launch(void* const* d_in, const int* in_sizes, int n_in,
                              void* d_out, int out_size) {
    const float* Q = (const float*)d_in[0];
    const float* K = (const float*)d_in[1];
    const float* V = (const float*)d_in[2];
    float*       O = (float*)d_out;

    const int smem = (2 * 64 * SROW + 4 * 32 * SROW) * (int)sizeof(__nv_bfloat16);  // 40960 B
    cudaFuncSetAttribute(attn_kernel, cudaFuncAttributeMaxDynamicSharedMemorySize, smem);

    sketch_kernel<<<dim3(B_H, 8), 256>>>(K, V);
    attn_kernel<<<dim3(SEQ / 128, B_H), 128, smem>>>(Q, V, O);
}

// round 5
// speedup vs baseline: 5.1931x; 1.2585x over previous
#include <cuda_runtime.h>
#include <cuda_bf16.h>
#include <cstdint>

// Problem constants (B=4, H=16, N=4096, D=64, M2=512, N/M2=8)
#define B_H   64
#define SEQ   4096
#define DIM   64
#define M2C   512
#define SROW  80    // smem row stride in bf16; 160B stride -> conflict-free LDS.64 frags

// Scratch sketches in bf16, 1/8 scale pre-applied, contraction dim pair-interleaved:
// within each 16-elem k-group, pair p=(k>>1)&7 sits at phys pair 2*(p&3)+(p>>2),
// so a thread's (k=2t4, k=2t4+8) fragment pairs are adjacent -> one LDS.64.
__device__ __nv_bfloat16 g_sks[B_H * M2C * DIM];   // [bh][m'][a~]
__device__ __nv_bfloat16 g_stv[B_H * DIM * M2C];   // [bh][e][m'~]

__device__ __forceinline__ int ileave16(int k) {
    int p = (k >> 1) & 7;
    return (k & ~15) + ((2 * (p & 3) + (p >> 2)) << 1) + (k & 1);
}
__device__ __forceinline__ float ex2(float x) {
    float y; asm("ex2.approx.f32 %0, %1;" : "=f"(y) : "f"(x)); return y;
}
__device__ __forceinline__ uint32_t pack_bf2(float lo, float hi) {
    __nv_bfloat162 h = __floats2bfloat162_rn(lo, hi);
    return *(uint32_t*)&h;
}
__device__ __forceinline__ void mma_bf16(float c[4],
        uint32_t a0, uint32_t a1, uint32_t a2, uint32_t a3,
        uint32_t b0, uint32_t b1) {
    asm volatile(
        "mma.sync.aligned.m16n8k16.row.col.f32.bf16.bf16.f32 "
        "{%0,%1,%2,%3}, {%4,%5,%6,%7}, {%8,%9}, {%0,%1,%2,%3};\n"
        : "+f"(c[0]), "+f"(c[1]), "+f"(c[2]), "+f"(c[3])
        : "r"(a0), "r"(a1), "r"(a2), "r"(a3), "r"(b0), "r"(b1));
}
__device__ __forceinline__ void cpa16(uint32_t s, const void* g) {
    asm volatile("cp.async.cg.shared.global [%0], [%1], 16;" :: "r"(s), "l"(g));
}

// ---------------------------------------------------------------------------
// Kernel 1: build sketches, m' = r*64 + d permutation (softmax-invariant; the
// same permutation is applied to SKS and STV so the result is exact).
//   SKS_P[m'][a~] = (1/8) sum_j K[r*512 + j*64 + a][d]
//   STV_P[e][m'~] = (1/8) sum_j V[(d*8+r)*8 + j][e]
// ---------------------------------------------------------------------------
__global__ __launch_bounds__(256) void sketch_kernel(const float* __restrict__ K,
                                                     const float* __restrict__ V) {
    __shared__ float acc[64 * 65];
    const int bh = blockIdx.x, r = blockIdx.y;
    const float* Kb = K + (size_t)bh * SEQ * DIM;
    const float* Vb = V + (size_t)bh * SEQ * DIM;
    __nv_bfloat16* sks = g_sks + (size_t)bh * M2C * DIM;
    __nv_bfloat16* stv = g_stv + (size_t)bh * DIM * M2C;
    const int tid = threadIdx.x;

    for (int l = tid; l < 4096; l += 256) {            // acc[a][d]
        int a = l >> 6, d = l & 63;
        float s = 0.f;
        #pragma unroll
        for (int j = 0; j < 8; j++) s += Kb[(r * 512 + j * 64 + a) * 64 + d];
        acc[a * 65 + d] = s;
    }
    __syncthreads();
    for (int l = tid; l < 4096; l += 256) {
        int d = l >> 6, a = l & 63;
        sks[(r * 64 + d) * 64 + ileave16(a)] = __float2bfloat16_rn(acc[a * 65 + d] * 0.125f);
    }
    __syncthreads();
    for (int l = tid; l < 4096; l += 256) {            // acc[d][e]
        int d = l >> 6, e = l & 63;
        float s = 0.f;
        #pragma unroll
        for (int j = 0; j < 8; j++) s += Vb[((d * 8 + r) * 8 + j) * 64 + e];
        acc[d * 65 + e] = s;
    }
    __syncthreads();
    for (int l = tid; l < 4096; l += 256) {
        int e = l >> 6, d = l & 63;
        stv[e * 512 + r * 64 + ileave16(d)] = __float2bfloat16_rn(acc[d * 65 + e] * 0.125f);
    }
}

// ---------------------------------------------------------------------------
// Kernel 2: out = softmax(Q SKS^T / 8) @ STV + V  via bf16 m16n8k16 mma.sync.
// 128 threads (4 warps); warp owns 32 query rows. 8 chunks of 64 sketch cols,
// Ks/Vs double-buffered with a 2-stage cp.async pipeline so gmem latency
// overlaps the previous chunk's MMAs. exp via MUFU.EX2 (log2e/8 folded into Q).
// P round-trips through warp-private smem as bf16 (no barrier needed).
// ---------------------------------------------------------------------------
#define KVSZ (2 * 64 * SROW)    // one Ks+Vs buffer, in bf16 elems

__global__ __launch_bounds__(128, 3) void attn_kernel(const float* __restrict__ Q,
                                                      const float* __restrict__ V,
                                                      float* __restrict__ Out) {
    extern __shared__ __align__(16) char smb[];
    __nv_bfloat16* kvbuf = (__nv_bfloat16*)smb;              // [2][KVSZ]
    __nv_bfloat16* Ps    = kvbuf + 2 * KVSZ;                 // 4 warps x [32][SROW]

    const int tid  = threadIdx.x;
    const int lane = tid & 31, warp = tid >> 5;
    const int g = lane >> 2, t4 = lane & 3;
    const int bh   = blockIdx.y;
    const int wrow = blockIdx.x * 128 + warp * 32;

    const float* Qb = Q + (size_t)bh * SEQ * DIM;
    const __nv_bfloat16* sksb = g_sks + (size_t)bh * M2C * DIM;
    const __nv_bfloat16* stvb = g_stv + (size_t)bh * DIM * M2C;
    __nv_bfloat16* Pw = Ps + warp * 32 * SROW;

    // Stage chunk-c tiles into buffer buf via cp.async (8 x 16B per thread).
    auto stage = [&](int c, __nv_bfloat16* buf) {
        __nv_bfloat16* Kd = buf;
        __nv_bfloat16* Vd = buf + 64 * SROW;
        const int mc0 = c * 64;
        #pragma unroll
        for (int i = 0; i < 4; i++) {
            int l = tid + i * 128;
            int row = l >> 3, seg = (l & 7) * 8;
            cpa16((uint32_t)__cvta_generic_to_shared(&Kd[row * SROW + seg]),
                  &sksb[(mc0 + row) * 64 + seg]);
            cpa16((uint32_t)__cvta_generic_to_shared(&Vd[row * SROW + seg]),
                  &stvb[row * 512 + mc0 + seg]);
        }
        asm volatile("cp.async.commit_group;");
    };

    // Persistent Q fragments (both 16-row tiles); scale 0.125*log2(e) folded.
    const float qs = 0.125f * 1.4426950408889634f;
    uint32_t Qa[4][8];
    #pragma unroll
    for (int tt = 0; tt < 2; tt++) {
        const float* q0 = Qb + (size_t)(wrow + tt * 16 + g) * DIM;
        const float* q1 = Qb + (size_t)(wrow + tt * 16 + g + 8) * DIM;
        #pragma unroll
        for (int kk = 0; kk < 4; kk++) {
            float2 x0 = *(const float2*)&q0[kk * 16 + 2 * t4];
            float2 x1 = *(const float2*)&q1[kk * 16 + 2 * t4];
            float2 x2 = *(const float2*)&q0[kk * 16 + 2 * t4 + 8];
            float2 x3 = *(const float2*)&q1[kk * 16 + 2 * t4 + 8];
            Qa[kk][tt * 4 + 0] = pack_bf2(x0.x * qs, x0.y * qs);
            Qa[kk][tt * 4 + 1] = pack_bf2(x1.x * qs, x1.y * qs);
            Qa[kk][tt * 4 + 2] = pack_bf2(x2.x * qs, x2.y * qs);
            Qa[kk][tt * 4 + 3] = pack_bf2(x3.x * qs, x3.y * qs);
        }
    }

    float O0[8][4], O1[8][4];
    #pragma unroll
    for (int j = 0; j < 8; j++)
        #pragma unroll
        for (int c = 0; c < 4; c++) { O0[j][c] = 0.f; O1[j][c] = 0.f; }
    float sum0 = 0.f, sum1 = 0.f, sum2 = 0.f, sum3 = 0.f;

    stage(0, kvbuf);    // prologue: chunk 0 -> buffer 0

    for (int c = 0; c < 8; c++) {
        __nv_bfloat16* Ks = kvbuf + (c & 1) * KVSZ;
        __nv_bfloat16* Vs = Ks + 64 * SROW;

        // Issue next chunk's copies into the other buffer (its previous
        // contents were last read in iteration c-1, sealed by that
        // iteration's closing barrier).
        if (c + 1 < 8) {
            stage(c + 1, kvbuf + ((c + 1) & 1) * KVSZ);
            asm volatile("cp.async.wait_group 1;");
        } else {
            asm volatile("cp.async.wait_group 0;");
        }
        __syncthreads();   // chunk-c tiles visible to all warps

        // ---- GEMM1 (j pairs) + exp + P store ----
        #pragma unroll
        for (int jj = 0; jj < 4; jj++) {
            const int j0 = 2 * jj, j1 = 2 * jj + 1;
            float Sa[4] = {0,0,0,0}, Sb[4] = {0,0,0,0};   // tile0/tile1, col j0
            float Sc[4] = {0,0,0,0}, Sd[4] = {0,0,0,0};   // tile0/tile1, col j1
            #pragma unroll
            for (int kk = 0; kk < 4; kk++) {
                uint2 Bx = *(const uint2*)&Ks[(j0 * 8 + g) * SROW + kk * 16 + 4 * t4];
                uint2 By = *(const uint2*)&Ks[(j1 * 8 + g) * SROW + kk * 16 + 4 * t4];
                mma_bf16(Sa, Qa[kk][0], Qa[kk][1], Qa[kk][2], Qa[kk][3], Bx.x, Bx.y);
                mma_bf16(Sb, Qa[kk][4], Qa[kk][5], Qa[kk][6], Qa[kk][7], Bx.x, Bx.y);
                mma_bf16(Sc, Qa[kk][0], Qa[kk][1], Qa[kk][2], Qa[kk][3], By.x, By.y);
                mma_bf16(Sd, Qa[kk][4], Qa[kk][5], Qa[kk][6], Qa[kk][7], By.x, By.y);
            }
            #pragma unroll
            for (int h = 0; h < 2; h++) {                 // h=0 -> j0, h=1 -> j1
                const int j = h ? j1 : j0;
                float* S0 = h ? Sc : Sa;
                float* S1 = h ? Sd : Sb;
                float p00 = ex2(S0[0]), p01 = ex2(S0[1]);
                float p02 = ex2(S0[2]), p03 = ex2(S0[3]);
                float p10 = ex2(S1[0]), p11 = ex2(S1[1]);
                float p12 = ex2(S1[2]), p13 = ex2(S1[3]);
                sum0 += p00 + p01;  sum1 += p02 + p03;
                sum2 += p10 + p11;  sum3 += p12 + p13;
                // k = j*8 + 2t4 -> phys word (j>>1)*8 + 2t4 + (j&1), elems x2
                const int co = (j >> 1) * 16 + (2 * t4 + (j & 1)) * 2;
                *(uint32_t*)&Pw[(g     ) * SROW + co] = pack_bf2(p00, p01);
                *(uint32_t*)&Pw[(g +  8) * SROW + co] = pack_bf2(p02, p03);
                *(uint32_t*)&Pw[(g + 16) * SROW + co] = pack_bf2(p10, p11);
                *(uint32_t*)&Pw[(g + 24) * SROW + co] = pack_bf2(p12, p13);
            }
        }
        // Pw is warp-private; same-warp STS->LDS needs no barrier.

        // ---- GEMM2: O += P @ STV ----
        #pragma unroll
        for (int kk = 0; kk < 4; kk++) {
            uint2 uA = *(const uint2*)&Pw[(g     ) * SROW + kk * 16 + 4 * t4];
            uint2 uB = *(const uint2*)&Pw[(g +  8) * SROW + kk * 16 + 4 * t4];
            uint2 uC = *(const uint2*)&Pw[(g + 16) * SROW + kk * 16 + 4 * t4];
            uint2 uD = *(const uint2*)&Pw[(g + 24) * SROW + kk * 16 + 4 * t4];
            #pragma unroll
            for (int j = 0; j < 8; j++) {
                uint2 Bv = *(const uint2*)&Vs[(j * 8 + g) * SROW + kk * 16 + 4 * t4];
                mma_bf16(O0[j], uA.x, uB.x, uA.y, uB.y, Bv.x, Bv.y);
                mma_bf16(O1[j], uC.x, uD.x, uC.y, uD.y, Bv.x, Bv.y);
            }
        }
        __syncthreads();   // all warps done reading chunk-c tiles
    }

    // quad-reduce row sums (lanes 4g..4g+3 share rows)
    sum0 += __shfl_xor_sync(0xffffffffu, sum0, 1);
    sum0 += __shfl_xor_sync(0xffffffffu, sum0, 2);
    sum1 += __shfl_xor_sync(0xffffffffu, sum1, 1);
    sum1 += __shfl_xor_sync(0xffffffffu, sum1, 2);
    sum2 += __shfl_xor_sync(0xffffffffu, sum2, 1);
    sum2 += __shfl_xor_sync(0xffffffffu, sum2, 2);
    sum3 += __shfl_xor_sync(0xffffffffu, sum3, 1);
    sum3 += __shfl_xor_sync(0xffffffffu, sum3, 2);
    const float i0 = 1.f / sum0, i1 = 1.f / sum1, i2 = 1.f / sum2, i3 = 1.f / sum3;

    const float* Vb = V + (size_t)bh * SEQ * DIM;
    float* Ob = Out + (size_t)bh * SEQ * DIM;
    const size_t r0 = wrow + g, r1 = r0 + 8, r2 = r0 + 16, r3 = r0 + 24;
    #pragma unroll
    for (int j = 0; j < 8; j++) {
        int c = j * 8 + 2 * t4;
        float2 v0 = *(const float2*)&Vb[r0 * DIM + c];
        float2 v1 = *(const float2*)&Vb[r1 * DIM + c];
        float2 v2 = *(const float2*)&Vb[r2 * DIM + c];
        float2 v3 = *(const float2*)&Vb[r3 * DIM + c];
        *(float2*)&Ob[r0 * DIM + c] = make_float2(O0[j][0] * i0 + v0.x, O0[j][1] * i0 + v0.y);
        *(float2*)&Ob[r1 * DIM + c] = make_float2(O0[j][2] * i1 + v1.x, O0[j][3] * i1 + v1.y);
        *(float2*)&Ob[r2 * DIM + c] = make_float2(O1[j][0] * i2 + v2.x, O1[j][1] * i2 + v2.y);
        *(float2*)&Ob[r3 * DIM + c] = make_float2(O1[j][2] * i3 + v3.x, O1[j][3] * i3 + v3.y);
    }
}

extern "C" void kernel_launch(void* const* d_in, const int* in_sizes, int n_in,
                              void* d_out, int out_size) {
    const float* Q = (const float*)d_in[0];
    const float* K = (const float*)d_in[1];
    const float* V = (const float*)d_in[2];
    float*       O = (float*)d_out;

    const int smem = (2 * KVSZ + 4 * 32 * SROW) * (int)sizeof(__nv_bfloat16);  // 61440 B
    cudaFuncSetAttribute(attn_kernel, cudaFuncAttributeMaxDynamicSharedMemorySize, smem);

    sketch_kernel<<<dim3(B_H, 8), 256>>>(K, V);
    attn_kernel<<<dim3(SEQ / 128, B_H), 128, smem>>>(Q, V, O);
}

// round 6
// speedup vs baseline: 6.1281x; 1.1800x over previous
#include <cuda_runtime.h>
#include <cuda_bf16.h>
#include <cstdint>

// Problem constants (B=4, H=16, N=4096, D=64, M2=512, N/M2=8)
#define B_H   64
#define SEQ   4096
#define DIM   64
#define M2C   512
#define SROW  80    // smem row stride in bf16; 160B stride -> conflict-free LDS.64 frags

// Scratch sketches in bf16, 1/8 scale pre-applied, contraction dim pair-interleaved:
// within each 16-elem k-group, pair p=(k>>1)&7 sits at phys pair 2*(p&3)+(p>>2),
// so a thread's (k=2t4, k=2t4+8) fragment pairs are adjacent -> one LDS.64.
__device__ __nv_bfloat16 g_sks[B_H * M2C * DIM];   // [bh][m'][a~]
__device__ __nv_bfloat16 g_stv[B_H * DIM * M2C];   // [bh][e][m'~]

__device__ __forceinline__ float ex2(float x) {
    float y; asm("ex2.approx.f32 %0, %1;" : "=f"(y) : "f"(x)); return y;
}
__device__ __forceinline__ uint32_t pack_bf2(float lo, float hi) {
    __nv_bfloat162 h = __floats2bfloat162_rn(lo, hi);
    return *(uint32_t*)&h;
}
__device__ __forceinline__ void mma_bf16(float c[4],
        uint32_t a0, uint32_t a1, uint32_t a2, uint32_t a3,
        uint32_t b0, uint32_t b1) {
    asm volatile(
        "mma.sync.aligned.m16n8k16.row.col.f32.bf16.bf16.f32 "
        "{%0,%1,%2,%3}, {%4,%5,%6,%7}, {%8,%9}, {%0,%1,%2,%3};\n"
        : "+f"(c[0]), "+f"(c[1]), "+f"(c[2]), "+f"(c[3])
        : "r"(a0), "r"(a1), "r"(a2), "r"(a3), "r"(b0), "r"(b1));
}
__device__ __forceinline__ void cpa16(uint32_t s, const void* g) {
    asm volatile("cp.async.cg.shared.global [%0], [%1], 16;" :: "r"(s), "l"(g));
}

// ---------------------------------------------------------------------------
// Kernel 1: build sketches, m' = r*64 + d permutation (softmax-invariant; the
// same permutation is applied to SKS and STV so the result is exact).
//   SKS_P[m'][a~] = (1/8) sum_j K[r*512 + j*64 + a][d]
//   STV_P[e][m'~] = (1/8) sum_j V[(d*8+r)*8 + j][e]
// float4 gmem loads (MLP=8); writes pack interleaved pairs as bf16x2.
// ---------------------------------------------------------------------------
__global__ __launch_bounds__(256) void sketch_kernel(const float* __restrict__ K,
                                                     const float* __restrict__ V) {
    __shared__ float acc[64 * 65];
    const int bh = blockIdx.x, r = blockIdx.y;
    const float* Kb = K + (size_t)bh * SEQ * DIM;
    const float* Vb = V + (size_t)bh * SEQ * DIM;
    __nv_bfloat16* sks = g_sks + (size_t)bh * M2C * DIM;
    __nv_bfloat16* stv = g_stv + (size_t)bh * DIM * M2C;
    const int tid = threadIdx.x;

    // --- SKS: acc[a][d] = sum_j K[r*512+j*64+a][d] ---
    for (int l = tid; l < 1024; l += 256) {
        int a = l >> 4, d4 = (l & 15) << 2;
        float4 s = make_float4(0.f, 0.f, 0.f, 0.f);
        #pragma unroll
        for (int j = 0; j < 8; j++) {
            float4 x = *(const float4*)&Kb[(r * 512 + j * 64 + a) * 64 + d4];
            s.x += x.x; s.y += x.y; s.z += x.z; s.w += x.w;
        }
        float* dst = &acc[a * 65 + d4];
        dst[0] = s.x; dst[1] = s.y; dst[2] = s.z; dst[3] = s.w;
    }
    __syncthreads();
    for (int l = tid; l < 2048; l += 256) {       // pair p covers a=2p,2p+1
        int d = l >> 5, p = l & 31;
        float lo = acc[(2 * p    ) * 65 + d] * 0.125f;
        float hi = acc[(2 * p + 1) * 65 + d] * 0.125f;
        int q = p & 7;
        int phys = ((p >> 3) << 4) + ((2 * (q & 3) + (q >> 2)) << 1);
        *(uint32_t*)&sks[(r * 64 + d) * 64 + phys] = pack_bf2(lo, hi);
    }
    __syncthreads();
    // --- STV: acc[d][e] = sum_j V[(d*8+r)*8+j][e] ---
    for (int l = tid; l < 1024; l += 256) {
        int d = l >> 4, e4 = (l & 15) << 2;
        float4 s = make_float4(0.f, 0.f, 0.f, 0.f);
        #pragma unroll
        for (int j = 0; j < 8; j++) {
            float4 x = *(const float4*)&Vb[((d * 8 + r) * 8 + j) * 64 + e4];
            s.x += x.x; s.y += x.y; s.z += x.z; s.w += x.w;
        }
        float* dst = &acc[d * 65 + e4];
        dst[0] = s.x; dst[1] = s.y; dst[2] = s.z; dst[3] = s.w;
    }
    __syncthreads();
    for (int l = tid; l < 2048; l += 256) {       // pair p covers d=2p,2p+1
        int e = l >> 5, p = l & 31;
        float lo = acc[(2 * p    ) * 65 + e] * 0.125f;
        float hi = acc[(2 * p + 1) * 65 + e] * 0.125f;
        int q = p & 7;
        int phys = ((p >> 3) << 4) + ((2 * (q & 3) + (q >> 2)) << 1);
        *(uint32_t*)&stv[e * 512 + r * 64 + phys] = pack_bf2(lo, hi);
    }
}

// ---------------------------------------------------------------------------
// Kernel 2: out = softmax(Q SKS^T / 8) @ STV + V  via bf16 m16n8k16 mma.sync.
// 128 threads (4 warps); warp owns 32 query rows. 8 chunks of 64 sketch cols,
// double-buffered cp.async pipeline. P never leaves registers: the C-fragment
// layout of GEMM1's (j0,j1) output pair IS the A-fragment layout of GEMM2's
// k-group jj, so exp outputs pack directly into MMA A operands.
// exp via MUFU.EX2 (log2e/8 folded into Q).
// ---------------------------------------------------------------------------
#define KVSZ (2 * 64 * SROW)    // one Ks+Vs buffer, in bf16 elems

__global__ __launch_bounds__(128, 3) void attn_kernel(const float* __restrict__ Q,
                                                      const float* __restrict__ V,
                                                      float* __restrict__ Out) {
    extern __shared__ __align__(16) char smb[];
    __nv_bfloat16* kvbuf = (__nv_bfloat16*)smb;              // [2][KVSZ]

    const int tid  = threadIdx.x;
    const int lane = tid & 31, warp = tid >> 5;
    const int g = lane >> 2, t4 = lane & 3;
    const int bh   = blockIdx.y;
    const int wrow = blockIdx.x * 128 + warp * 32;

    const float* Qb = Q + (size_t)bh * SEQ * DIM;
    const __nv_bfloat16* sksb = g_sks + (size_t)bh * M2C * DIM;
    const __nv_bfloat16* stvb = g_stv + (size_t)bh * DIM * M2C;

    auto stage = [&](int c, __nv_bfloat16* buf) {
        __nv_bfloat16* Kd = buf;
        __nv_bfloat16* Vd = buf + 64 * SROW;
        const int mc0 = c * 64;
        #pragma unroll
        for (int i = 0; i < 4; i++) {
            int l = tid + i * 128;
            int row = l >> 3, seg = (l & 7) * 8;
            cpa16((uint32_t)__cvta_generic_to_shared(&Kd[row * SROW + seg]),
                  &sksb[(mc0 + row) * 64 + seg]);
            cpa16((uint32_t)__cvta_generic_to_shared(&Vd[row * SROW + seg]),
                  &stvb[row * 512 + mc0 + seg]);
        }
        asm volatile("cp.async.commit_group;");
    };

    // Persistent Q fragments (both 16-row tiles); scale 0.125*log2(e) folded.
    const float qs = 0.125f * 1.4426950408889634f;
    uint32_t Qa[4][8];
    #pragma unroll
    for (int tt = 0; tt < 2; tt++) {
        const float* q0 = Qb + (size_t)(wrow + tt * 16 + g) * DIM;
        const float* q1 = Qb + (size_t)(wrow + tt * 16 + g + 8) * DIM;
        #pragma unroll
        for (int kk = 0; kk < 4; kk++) {
            float2 x0 = *(const float2*)&q0[kk * 16 + 2 * t4];
            float2 x1 = *(const float2*)&q1[kk * 16 + 2 * t4];
            float2 x2 = *(const float2*)&q0[kk * 16 + 2 * t4 + 8];
            float2 x3 = *(const float2*)&q1[kk * 16 + 2 * t4 + 8];
            Qa[kk][tt * 4 + 0] = pack_bf2(x0.x * qs, x0.y * qs);
            Qa[kk][tt * 4 + 1] = pack_bf2(x1.x * qs, x1.y * qs);
            Qa[kk][tt * 4 + 2] = pack_bf2(x2.x * qs, x2.y * qs);
            Qa[kk][tt * 4 + 3] = pack_bf2(x3.x * qs, x3.y * qs);
        }
    }

    float O0[8][4], O1[8][4];
    #pragma unroll
    for (int j = 0; j < 8; j++)
        #pragma unroll
        for (int c = 0; c < 4; c++) { O0[j][c] = 0.f; O1[j][c] = 0.f; }
    float sum0 = 0.f, sum1 = 0.f, sum2 = 0.f, sum3 = 0.f;

    stage(0, kvbuf);    // prologue: chunk 0 -> buffer 0

    for (int c = 0; c < 8; c++) {
        __nv_bfloat16* Ks = kvbuf + (c & 1) * KVSZ;
        __nv_bfloat16* Vs = Ks + 64 * SROW;

        if (c + 1 < 8) {
            stage(c + 1, kvbuf + ((c + 1) & 1) * KVSZ);
            asm volatile("cp.async.wait_group 1;");
        } else {
            asm volatile("cp.async.wait_group 0;");
        }
        __syncthreads();   // chunk-c tiles visible to all warps

        const __nv_bfloat16* KsW = Ks + g * SROW + 4 * t4;   // hoisted frag bases
        const __nv_bfloat16* VsW = Vs + g * SROW + 4 * t4;

        #pragma unroll
        for (int jj = 0; jj < 4; jj++) {
            // ---- GEMM1: logits for j-pair (2jj, 2jj+1), both 16-row tiles ----
            float Sa[4] = {0,0,0,0}, Sb[4] = {0,0,0,0};   // tile0/tile1, col j0
            float Sc[4] = {0,0,0,0}, Sd[4] = {0,0,0,0};   // tile0/tile1, col j1
            #pragma unroll
            for (int kk = 0; kk < 4; kk++) {
                uint2 Bx = *(const uint2*)&KsW[(2 * jj    ) * 8 * SROW + kk * 16];
                uint2 By = *(const uint2*)&KsW[(2 * jj + 1) * 8 * SROW + kk * 16];
                mma_bf16(Sa, Qa[kk][0], Qa[kk][1], Qa[kk][2], Qa[kk][3], Bx.x, Bx.y);
                mma_bf16(Sb, Qa[kk][4], Qa[kk][5], Qa[kk][6], Qa[kk][7], Bx.x, Bx.y);
                mma_bf16(Sc, Qa[kk][0], Qa[kk][1], Qa[kk][2], Qa[kk][3], By.x, By.y);
                mma_bf16(Sd, Qa[kk][4], Qa[kk][5], Qa[kk][6], Qa[kk][7], By.x, By.y);
            }
            // ---- exp + pack: C-frag (j0,j1) == A-frag of GEMM2 k-group jj ----
            float pa0 = ex2(Sa[0]), pa1 = ex2(Sa[1]), pa2 = ex2(Sa[2]), pa3 = ex2(Sa[3]);
            float pb0 = ex2(Sb[0]), pb1 = ex2(Sb[1]), pb2 = ex2(Sb[2]), pb3 = ex2(Sb[3]);
            float pc0 = ex2(Sc[0]), pc1 = ex2(Sc[1]), pc2 = ex2(Sc[2]), pc3 = ex2(Sc[3]);
            float pd0 = ex2(Sd[0]), pd1 = ex2(Sd[1]), pd2 = ex2(Sd[2]), pd3 = ex2(Sd[3]);
            sum0 += pa0 + pa1 + pc0 + pc1;     // tile0 row g
            sum1 += pa2 + pa3 + pc2 + pc3;     // tile0 row g+8
            sum2 += pb0 + pb1 + pd0 + pd1;     // tile1 row g
            sum3 += pb2 + pb3 + pd2 + pd3;     // tile1 row g+8
            uint32_t a0 = pack_bf2(pa0, pa1), a1 = pack_bf2(pa2, pa3);
            uint32_t a2 = pack_bf2(pc0, pc1), a3 = pack_bf2(pc2, pc3);
            uint32_t a4 = pack_bf2(pb0, pb1), a5 = pack_bf2(pb2, pb3);
            uint32_t a6 = pack_bf2(pd0, pd1), a7 = pack_bf2(pd2, pd3);
            // ---- GEMM2 partial: O += P(:, kk=jj) @ STV(kk=jj, :) ----
            #pragma unroll
            for (int j = 0; j < 8; j++) {
                uint2 Bv = *(const uint2*)&VsW[j * 8 * SROW + jj * 16];
                mma_bf16(O0[j], a0, a1, a2, a3, Bv.x, Bv.y);
                mma_bf16(O1[j], a4, a5, a6, a7, Bv.x, Bv.y);
            }
        }
        __syncthreads();   // all warps done reading chunk-c tiles
    }

    // quad-reduce row sums (lanes 4g..4g+3 share rows)
    sum0 += __shfl_xor_sync(0xffffffffu, sum0, 1);
    sum0 += __shfl_xor_sync(0xffffffffu, sum0, 2);
    sum1 += __shfl_xor_sync(0xffffffffu, sum1, 1);
    sum1 += __shfl_xor_sync(0xffffffffu, sum1, 2);
    sum2 += __shfl_xor_sync(0xffffffffu, sum2, 1);
    sum2 += __shfl_xor_sync(0xffffffffu, sum2, 2);
    sum3 += __shfl_xor_sync(0xffffffffu, sum3, 1);
    sum3 += __shfl_xor_sync(0xffffffffu, sum3, 2);
    const float i0 = 1.f / sum0, i1 = 1.f / sum1, i2 = 1.f / sum2, i3 = 1.f / sum3;

    const float* Vb = V + (size_t)bh * SEQ * DIM;
    float* Ob = Out + (size_t)bh * SEQ * DIM;
    const size_t r0 = wrow + g, r1 = r0 + 8, r2 = r0 + 16, r3 = r0 + 24;
    #pragma unroll
    for (int j = 0; j < 8; j++) {
        int cix = j * 8 + 2 * t4;
        float2 v0 = *(const float2*)&Vb[r0 * DIM + cix];
        float2 v1 = *(const float2*)&Vb[r1 * DIM + cix];
        float2 v2 = *(const float2*)&Vb[r2 * DIM + cix];
        float2 v3 = *(const float2*)&Vb[r3 * DIM + cix];
        *(float2*)&Ob[r0 * DIM + cix] = make_float2(O0[j][0] * i0 + v0.x, O0[j][1] * i0 + v0.y);
        *(float2*)&Ob[r1 * DIM + cix] = make_float2(O0[j][2] * i1 + v1.x, O0[j][3] * i1 + v1.y);
        *(float2*)&Ob[r2 * DIM + cix] = make_float2(O1[j][0] * i2 + v2.x, O1[j][1] * i2 + v2.y);
        *(float2*)&Ob[r3 * DIM + cix] = make_float2(O1[j][2] * i3 + v3.x, O1[j][3] * i3 + v3.y);
    }
}

extern "C" void kernel_launch(void* const* d_in, const int* in_sizes, int n_in,
                              void* d_out, int out_size) {
    const float* Q = (const float*)d_in[0];
    const float* K = (const float*)d_in[1];
    const float* V = (const float*)d_in[2];
    float*       O = (float*)d_out;

    const int smem = 2 * KVSZ * (int)sizeof(__nv_bfloat16);   // 40960 B
    cudaFuncSetAttribute(attn_kernel, cudaFuncAttributeMaxDynamicSharedMemorySize, smem);

    sketch_kernel<<<dim3(B_H, 8), 256>>>(K, V);
    attn_kernel<<<dim3(SEQ / 128, B_H), 128, smem>>>(Q, V, O);
}

// round 7
// speedup vs baseline: 6.1405x; 1.0020x over previous
#include <cuda_runtime.h>
#include <cuda_bf16.h>
#include <cstdint>

// Problem constants (B=4, H=16, N=4096, D=64, M2=512, N/M2=8)
#define B_H   64
#define SEQ   4096
#define DIM   64
#define M2C   512
#define SROW  80    // smem row stride in bf16; 160B stride -> conflict-free LDS.64 frags

// Scratch sketches in bf16, 1/8 scale pre-applied, contraction dim pair-interleaved:
// within each 16-elem k-group, pair p=(k>>1)&7 sits at phys pair 2*(p&3)+(p>>2),
// so a thread's (k=2t4, k=2t4+8) fragment pairs are adjacent -> one LDS.64.
__device__ __nv_bfloat16 g_sks[B_H * M2C * DIM];   // [bh][m'][a~]
__device__ __nv_bfloat16 g_stv[B_H * DIM * M2C];   // [bh][e][m'~]

__device__ __forceinline__ float ex2(float x) {
    float y; asm("ex2.approx.f32 %0, %1;" : "=f"(y) : "f"(x)); return y;
}
__device__ __forceinline__ uint32_t pack_bf2(float lo, float hi) {
    __nv_bfloat162 h = __floats2bfloat162_rn(lo, hi);
    return *(uint32_t*)&h;
}
__device__ __forceinline__ void mma_bf16(float c[4],
        uint32_t a0, uint32_t a1, uint32_t a2, uint32_t a3,
        uint32_t b0, uint32_t b1) {
    asm volatile(
        "mma.sync.aligned.m16n8k16.row.col.f32.bf16.bf16.f32 "
        "{%0,%1,%2,%3}, {%4,%5,%6,%7}, {%8,%9}, {%0,%1,%2,%3};\n"
        : "+f"(c[0]), "+f"(c[1]), "+f"(c[2]), "+f"(c[3])
        : "r"(a0), "r"(a1), "r"(a2), "r"(a3), "r"(b0), "r"(b1));
}
__device__ __forceinline__ void cpa16(uint32_t s, const void* g) {
    asm volatile("cp.async.cg.shared.global [%0], [%1], 16;" :: "r"(s), "l"(g));
}

// ---------------------------------------------------------------------------
// Kernel 1: build sketches, m' = r*64 + d permutation (softmax-invariant; the
// same permutation is applied to SKS and STV so the result is exact).
//   SKS_P[m'][a~] = (1/8) sum_j K[r*512 + j*64 + a][d]
//   STV_P[e][m'~] = (1/8) sum_j V[(d*8+r)*8 + j][e]
// float4 gmem loads (MLP=8); writes pack interleaved pairs as bf16x2.
// ---------------------------------------------------------------------------
__global__ __launch_bounds__(256) void sketch_kernel(const float* __restrict__ K,
                                                     const float* __restrict__ V) {
    __shared__ float acc[64 * 65];
    const int bh = blockIdx.x, r = blockIdx.y;
    const float* Kb = K + (size_t)bh * SEQ * DIM;
    const float* Vb = V + (size_t)bh * SEQ * DIM;
    __nv_bfloat16* sks = g_sks + (size_t)bh * M2C * DIM;
    __nv_bfloat16* stv = g_stv + (size_t)bh * DIM * M2C;
    const int tid = threadIdx.x;

    // --- SKS: acc[a][d] = sum_j K[r*512+j*64+a][d] ---
    for (int l = tid; l < 1024; l += 256) {
        int a = l >> 4, d4 = (l & 15) << 2;
        float4 s = make_float4(0.f, 0.f, 0.f, 0.f);
        #pragma unroll
        for (int j = 0; j < 8; j++) {
            float4 x = *(const float4*)&Kb[(r * 512 + j * 64 + a) * 64 + d4];
            s.x += x.x; s.y += x.y; s.z += x.z; s.w += x.w;
        }
        float* dst = &acc[a * 65 + d4];
        dst[0] = s.x; dst[1] = s.y; dst[2] = s.z; dst[3] = s.w;
    }
    __syncthreads();
    for (int l = tid; l < 2048; l += 256) {       // pair p covers a=2p,2p+1
        int d = l >> 5, p = l & 31;
        float lo = acc[(2 * p    ) * 65 + d] * 0.125f;
        float hi = acc[(2 * p + 1) * 65 + d] * 0.125f;
        int q = p & 7;
        int phys = ((p >> 3) << 4) + ((2 * (q & 3) + (q >> 2)) << 1);
        *(uint32_t*)&sks[(r * 64 + d) * 64 + phys] = pack_bf2(lo, hi);
    }
    __syncthreads();
    // --- STV: acc[d][e] = sum_j V[(d*8+r)*8+j][e] ---
    for (int l = tid; l < 1024; l += 256) {
        int d = l >> 4, e4 = (l & 15) << 2;
        float4 s = make_float4(0.f, 0.f, 0.f, 0.f);
        #pragma unroll
        for (int j = 0; j < 8; j++) {
            float4 x = *(const float4*)&Vb[((d * 8 + r) * 8 + j) * 64 + e4];
            s.x += x.x; s.y += x.y; s.z += x.z; s.w += x.w;
        }
        float* dst = &acc[d * 65 + e4];
        dst[0] = s.x; dst[1] = s.y; dst[2] = s.z; dst[3] = s.w;
    }
    __syncthreads();
    for (int l = tid; l < 2048; l += 256) {       // pair p covers d=2p,2p+1
        int e = l >> 5, p = l & 31;
        float lo = acc[(2 * p    ) * 65 + e] * 0.125f;
        float hi = acc[(2 * p + 1) * 65 + e] * 0.125f;
        int q = p & 7;
        int phys = ((p >> 3) << 4) + ((2 * (q & 3) + (q >> 2)) << 1);
        *(uint32_t*)&stv[e * 512 + r * 64 + phys] = pack_bf2(lo, hi);
    }
}

// ---------------------------------------------------------------------------
// Kernel 2: out = softmax(Q SKS^T / 8) @ STV + V  via bf16 m16n8k16 mma.sync.
// 128 threads (4 warps); warp owns 32 query rows. 8 chunks of 64 sketch cols,
// double-buffered cp.async pipeline. P never leaves registers: the C-fragment
// layout of GEMM1's (j0,j1) output pair IS the A-fragment layout of GEMM2's
// k-group jj, so exp outputs pack directly into MMA A operands.
// exp via MUFU.EX2 (log2e/8 folded into Q).
// ---------------------------------------------------------------------------
#define KVSZ (2 * 64 * SROW)    // one Ks+Vs buffer, in bf16 elems

__global__ __launch_bounds__(128, 3) void attn_kernel(const float* __restrict__ Q,
                                                      const float* __restrict__ V,
                                                      float* __restrict__ Out) {
    extern __shared__ __align__(16) char smb[];
    __nv_bfloat16* kvbuf = (__nv_bfloat16*)smb;              // [2][KVSZ]

    const int tid  = threadIdx.x;
    const int lane = tid & 31, warp = tid >> 5;
    const int g = lane >> 2, t4 = lane & 3;
    const int bh   = blockIdx.y;
    const int wrow = blockIdx.x * 128 + warp * 32;

    const float* Qb = Q + (size_t)bh * SEQ * DIM;
    const __nv_bfloat16* sksb = g_sks + (size_t)bh * M2C * DIM;
    const __nv_bfloat16* stvb = g_stv + (size_t)bh * DIM * M2C;

    auto stage = [&](int c, __nv_bfloat16* buf) {
        __nv_bfloat16* Kd = buf;
        __nv_bfloat16* Vd = buf + 64 * SROW;
        const int mc0 = c * 64;
        #pragma unroll
        for (int i = 0; i < 4; i++) {
            int l = tid + i * 128;
            int row = l >> 3, seg = (l & 7) * 8;
            cpa16((uint32_t)__cvta_generic_to_shared(&Kd[row * SROW + seg]),
                  &sksb[(mc0 + row) * 64 + seg]);
            cpa16((uint32_t)__cvta_generic_to_shared(&Vd[row * SROW + seg]),
                  &stvb[row * 512 + mc0 + seg]);
        }
        asm volatile("cp.async.commit_group;");
    };

    // Persistent Q fragments (both 16-row tiles); scale 0.125*log2(e) folded.
    const float qs = 0.125f * 1.4426950408889634f;
    uint32_t Qa[4][8];
    #pragma unroll
    for (int tt = 0; tt < 2; tt++) {
        const float* q0 = Qb + (size_t)(wrow + tt * 16 + g) * DIM;
        const float* q1 = Qb + (size_t)(wrow + tt * 16 + g + 8) * DIM;
        #pragma unroll
        for (int kk = 0; kk < 4; kk++) {
            float2 x0 = *(const float2*)&q0[kk * 16 + 2 * t4];
            float2 x1 = *(const float2*)&q1[kk * 16 + 2 * t4];
            float2 x2 = *(const float2*)&q0[kk * 16 + 2 * t4 + 8];
            float2 x3 = *(const float2*)&q1[kk * 16 + 2 * t4 + 8];
            Qa[kk][tt * 4 + 0] = pack_bf2(x0.x * qs, x0.y * qs);
            Qa[kk][tt * 4 + 1] = pack_bf2(x1.x * qs, x1.y * qs);
            Qa[kk][tt * 4 + 2] = pack_bf2(x2.x * qs, x2.y * qs);
            Qa[kk][tt * 4 + 3] = pack_bf2(x3.x * qs, x3.y * qs);
        }
    }

    float O0[8][4], O1[8][4];
    #pragma unroll
    for (int j = 0; j < 8; j++)
        #pragma unroll
        for (int c = 0; c < 4; c++) { O0[j][c] = 0.f; O1[j][c] = 0.f; }
    float sum0 = 0.f, sum1 = 0.f, sum2 = 0.f, sum3 = 0.f;

    stage(0, kvbuf);    // prologue: chunk 0 -> buffer 0

    for (int c = 0; c < 8; c++) {
        __nv_bfloat16* Ks = kvbuf + (c & 1) * KVSZ;
        __nv_bfloat16* Vs = Ks + 64 * SROW;

        if (c + 1 < 8) {
            stage(c + 1, kvbuf + ((c + 1) & 1) * KVSZ);
            asm volatile("cp.async.wait_group 1;");
        } else {
            asm volatile("cp.async.wait_group 0;");
        }
        __syncthreads();   // chunk-c tiles visible to all warps

        const __nv_bfloat16* KsW = Ks + g * SROW + 4 * t4;   // hoisted frag bases
        const __nv_bfloat16* VsW = Vs + g * SROW + 4 * t4;

        #pragma unroll
        for (int jj = 0; jj < 4; jj++) {
            // ---- GEMM1: logits for j-pair (2jj, 2jj+1), both 16-row tiles ----
            float Sa[4] = {0,0,0,0}, Sb[4] = {0,0,0,0};   // tile0/tile1, col j0
            float Sc[4] = {0,0,0,0}, Sd[4] = {0,0,0,0};   // tile0/tile1, col j1
            #pragma unroll
            for (int kk = 0; kk < 4; kk++) {
                uint2 Bx = *(const uint2*)&KsW[(2 * jj    ) * 8 * SROW + kk * 16];
                uint2 By = *(const uint2*)&KsW[(2 * jj + 1) * 8 * SROW + kk * 16];
                mma_bf16(Sa, Qa[kk][0], Qa[kk][1], Qa[kk][2], Qa[kk][3], Bx.x, Bx.y);
                mma_bf16(Sb, Qa[kk][4], Qa[kk][5], Qa[kk][6], Qa[kk][7], Bx.x, Bx.y);
                mma_bf16(Sc, Qa[kk][0], Qa[kk][1], Qa[kk][2], Qa[kk][3], By.x, By.y);
                mma_bf16(Sd, Qa[kk][4], Qa[kk][5], Qa[kk][6], Qa[kk][7], By.x, By.y);
            }
            // ---- exp + pack: C-frag (j0,j1) == A-frag of GEMM2 k-group jj ----
            float pa0 = ex2(Sa[0]), pa1 = ex2(Sa[1]), pa2 = ex2(Sa[2]), pa3 = ex2(Sa[3]);
            float pb0 = ex2(Sb[0]), pb1 = ex2(Sb[1]), pb2 = ex2(Sb[2]), pb3 = ex2(Sb[3]);
            float pc0 = ex2(Sc[0]), pc1 = ex2(Sc[1]), pc2 = ex2(Sc[2]), pc3 = ex2(Sc[3]);
            float pd0 = ex2(Sd[0]), pd1 = ex2(Sd[1]), pd2 = ex2(Sd[2]), pd3 = ex2(Sd[3]);
            sum0 += pa0 + pa1 + pc0 + pc1;     // tile0 row g
            sum1 += pa2 + pa3 + pc2 + pc3;     // tile0 row g+8
            sum2 += pb0 + pb1 + pd0 + pd1;     // tile1 row g
            sum3 += pb2 + pb3 + pd2 + pd3;     // tile1 row g+8
            uint32_t a0 = pack_bf2(pa0, pa1), a1 = pack_bf2(pa2, pa3);
            uint32_t a2 = pack_bf2(pc0, pc1), a3 = pack_bf2(pc2, pc3);
            uint32_t a4 = pack_bf2(pb0, pb1), a5 = pack_bf2(pb2, pb3);
            uint32_t a6 = pack_bf2(pd0, pd1), a7 = pack_bf2(pd2, pd3);
            // ---- GEMM2 partial: O += P(:, kk=jj) @ STV(kk=jj, :) ----
            #pragma unroll
            for (int j = 0; j < 8; j++) {
                uint2 Bv = *(const uint2*)&VsW[j * 8 * SROW + jj * 16];
                mma_bf16(O0[j], a0, a1, a2, a3, Bv.x, Bv.y);
                mma_bf16(O1[j], a4, a5, a6, a7, Bv.x, Bv.y);
            }
        }
        __syncthreads();   // all warps done reading chunk-c tiles
    }

    // quad-reduce row sums (lanes 4g..4g+3 share rows)
    sum0 += __shfl_xor_sync(0xffffffffu, sum0, 1);
    sum0 += __shfl_xor_sync(0xffffffffu, sum0, 2);
    sum1 += __shfl_xor_sync(0xffffffffu, sum1, 1);
    sum1 += __shfl_xor_sync(0xffffffffu, sum1, 2);
    sum2 += __shfl_xor_sync(0xffffffffu, sum2, 1);
    sum2 += __shfl_xor_sync(0xffffffffu, sum2, 2);
    sum3 += __shfl_xor_sync(0xffffffffu, sum3, 1);
    sum3 += __shfl_xor_sync(0xffffffffu, sum3, 2);
    const float i0 = 1.f / sum0, i1 = 1.f / sum1, i2 = 1.f / sum2, i3 = 1.f / sum3;

    const float* Vb = V + (size_t)bh * SEQ * DIM;
    float* Ob = Out + (size_t)bh * SEQ * DIM;
    const size_t r0 = wrow + g, r1 = r0 + 8, r2 = r0 + 16, r3 = r0 + 24;
    #pragma unroll
    for (int j = 0; j < 8; j++) {
        int cix = j * 8 + 2 * t4;
        float2 v0 = *(const float2*)&Vb[r0 * DIM + cix];
        float2 v1 = *(const float2*)&Vb[r1 * DIM + cix];
        float2 v2 = *(const float2*)&Vb[r2 * DIM + cix];
        float2 v3 = *(const float2*)&Vb[r3 * DIM + cix];
        *(float2*)&Ob[r0 * DIM + cix] = make_float2(O0[j][0] * i0 + v0.x, O0[j][1] * i0 + v0.y);
        *(float2*)&Ob[r1 * DIM + cix] = make_float2(O0[j][2] * i1 + v1.x, O0[j][3] * i1 + v1.y);
        *(float2*)&Ob[r2 * DIM + cix] = make_float2(O1[j][0] * i2 + v2.x, O1[j][1] * i2 + v2.y);
        *(float2*)&Ob[r3 * DIM + cix] = make_float2(O1[j][2] * i3 + v3.x, O1[j][3] * i3 + v3.y);
    }
}

extern "C" void kernel_launch(void* const* d_in, const int* in_sizes, int n_in,
                              void* d_out, int out_size) {
    const float* Q = (const float*)d_in[0];
    const float* K = (const float*)d_in[1];
    const float* V = (const float*)d_in[2];
    float*       O = (float*)d_out;

    const int smem = 2 * KVSZ * (int)sizeof(__nv_bfloat16);   // 40960 B
    cudaFuncSetAttribute(attn_kernel, cudaFuncAttributeMaxDynamicSharedMemorySize, smem);

    sketch_kernel<<<dim3(B_H, 8), 256>>>(K, V);
    attn_kernel<<<dim3(SEQ / 128, B_H), 128, smem>>>(Q, V, O);
}

// round 8
// speedup vs baseline: 6.1419x; 1.0002x over previous
#include <cuda_runtime.h>
#include <cuda_bf16.h>
#include <cstdint>

// Problem constants (B=4, H=16, N=4096, D=64, M2=512, N/M2=8)
#define B_H   64
#define SEQ   4096
#define DIM   64
#define M2C   512
#define SROW  80    // smem row stride in bf16; 160B stride -> conflict-free LDS.64 frags

// Scratch sketches in bf16, 1/8 scale pre-applied, contraction dim pair-interleaved:
// within each 16-elem k-group, pair p=(k>>1)&7 sits at phys pair 2*(p&3)+(p>>2),
// so a thread's (k=2t4, k=2t4+8) fragment pairs are adjacent -> one LDS.64.
__device__ __nv_bfloat16 g_sks[B_H * M2C * DIM];   // [bh][m'][a~]
__device__ __nv_bfloat16 g_stv[B_H * DIM * M2C];   // [bh][e][m'~]

__device__ __forceinline__ float ex2(float x) {
    float y; asm("ex2.approx.f32 %0, %1;" : "=f"(y) : "f"(x)); return y;
}
__device__ __forceinline__ uint32_t pack_bf2(float lo, float hi) {
    __nv_bfloat162 h = __floats2bfloat162_rn(lo, hi);
    return *(uint32_t*)&h;
}
__device__ __forceinline__ void mma_bf16(float c[4],
        uint32_t a0, uint32_t a1, uint32_t a2, uint32_t a3,
        uint32_t b0, uint32_t b1) {
    asm volatile(
        "mma.sync.aligned.m16n8k16.row.col.f32.bf16.bf16.f32 "
        "{%0,%1,%2,%3}, {%4,%5,%6,%7}, {%8,%9}, {%0,%1,%2,%3};\n"
        : "+f"(c[0]), "+f"(c[1]), "+f"(c[2]), "+f"(c[3])
        : "r"(a0), "r"(a1), "r"(a2), "r"(a3), "r"(b0), "r"(b1));
}
__device__ __forceinline__ void cpa16(uint32_t s, const void* g) {
    asm volatile("cp.async.cg.shared.global [%0], [%1], 16;" :: "r"(s), "l"(g));
}

// ---------------------------------------------------------------------------
// Kernel 1: build sketches, m' = r*64 + d permutation (softmax-invariant; the
// same permutation is applied to SKS and STV so the result is exact).
//   SKS_P[m'][a~] = (1/8) sum_j K[r*512 + j*64 + a][d]
//   STV_P[e][m'~] = (1/8) sum_j V[(d*8+r)*8 + j][e]
// float4 gmem loads (MLP=8); writes pack interleaved pairs as bf16x2.
// ---------------------------------------------------------------------------
__global__ __launch_bounds__(256) void sketch_kernel(const float* __restrict__ K,
                                                     const float* __restrict__ V) {
    __shared__ float acc[64 * 65];
    const int bh = blockIdx.x, r = blockIdx.y;
    const float* Kb = K + (size_t)bh * SEQ * DIM;
    const float* Vb = V + (size_t)bh * SEQ * DIM;
    __nv_bfloat16* sks = g_sks + (size_t)bh * M2C * DIM;
    __nv_bfloat16* stv = g_stv + (size_t)bh * DIM * M2C;
    const int tid = threadIdx.x;

    // --- SKS: acc[a][d] = sum_j K[r*512+j*64+a][d] ---
    for (int l = tid; l < 1024; l += 256) {
        int a = l >> 4, d4 = (l & 15) << 2;
        float4 s = make_float4(0.f, 0.f, 0.f, 0.f);
        #pragma unroll
        for (int j = 0; j < 8; j++) {
            float4 x = *(const float4*)&Kb[(r * 512 + j * 64 + a) * 64 + d4];
            s.x += x.x; s.y += x.y; s.z += x.z; s.w += x.w;
        }
        float* dst = &acc[a * 65 + d4];
        dst[0] = s.x; dst[1] = s.y; dst[2] = s.z; dst[3] = s.w;
    }
    __syncthreads();
    for (int l = tid; l < 2048; l += 256) {       // pair p covers a=2p,2p+1
        int d = l >> 5, p = l & 31;
        float lo = acc[(2 * p    ) * 65 + d] * 0.125f;
        float hi = acc[(2 * p + 1) * 65 + d] * 0.125f;
        int q = p & 7;
        int phys = ((p >> 3) << 4) + ((2 * (q & 3) + (q >> 2)) << 1);
        *(uint32_t*)&sks[(r * 64 + d) * 64 + phys] = pack_bf2(lo, hi);
    }
    __syncthreads();
    // --- STV: acc[d][e] = sum_j V[(d*8+r)*8+j][e] ---
    for (int l = tid; l < 1024; l += 256) {
        int d = l >> 4, e4 = (l & 15) << 2;
        float4 s = make_float4(0.f, 0.f, 0.f, 0.f);
        #pragma unroll
        for (int j = 0; j < 8; j++) {
            float4 x = *(const float4*)&Vb[((d * 8 + r) * 8 + j) * 64 + e4];
            s.x += x.x; s.y += x.y; s.z += x.z; s.w += x.w;
        }
        float* dst = &acc[d * 65 + e4];
        dst[0] = s.x; dst[1] = s.y; dst[2] = s.z; dst[3] = s.w;
    }
    __syncthreads();
    for (int l = tid; l < 2048; l += 256) {       // pair p covers d=2p,2p+1
        int e = l >> 5, p = l & 31;
        float lo = acc[(2 * p    ) * 65 + e] * 0.125f;
        float hi = acc[(2 * p + 1) * 65 + e] * 0.125f;
        int q = p & 7;
        int phys = ((p >> 3) << 4) + ((2 * (q & 3) + (q >> 2)) << 1);
        *(uint32_t*)&stv[e * 512 + r * 64 + phys] = pack_bf2(lo, hi);
    }
}

// ---------------------------------------------------------------------------
// Kernel 2: out = softmax(Q SKS^T / 8) @ STV + V  via bf16 m16n8k16 mma.sync.
// 128 threads (4 warps); warp owns 32 query rows. 8 chunks of 64 sketch cols,
// double-buffered cp.async pipeline. P never leaves registers: the C-fragment
// layout of GEMM1's (j0,j1) output pair IS the A-fragment layout of GEMM2's
// k-group jj, so exp outputs pack directly into MMA A operands.
// exp via MUFU.EX2 (log2e/8 folded into Q).
// ---------------------------------------------------------------------------
#define KVSZ (2 * 64 * SROW)    // one Ks+Vs buffer, in bf16 elems

__global__ __launch_bounds__(128, 3) void attn_kernel(const float* __restrict__ Q,
                                                      const float* __restrict__ V,
                                                      float* __restrict__ Out) {
    extern __shared__ __align__(16) char smb[];
    __nv_bfloat16* kvbuf = (__nv_bfloat16*)smb;              // [2][KVSZ]

    const int tid  = threadIdx.x;
    const int lane = tid & 31, warp = tid >> 5;
    const int g = lane >> 2, t4 = lane & 3;
    const int bh   = blockIdx.y;
    const int wrow = blockIdx.x * 128 + warp * 32;

    const float* Qb = Q + (size_t)bh * SEQ * DIM;
    const __nv_bfloat16* sksb = g_sks + (size_t)bh * M2C * DIM;
    const __nv_bfloat16* stvb = g_stv + (size_t)bh * DIM * M2C;

    auto stage = [&](int c, __nv_bfloat16* buf) {
        __nv_bfloat16* Kd = buf;
        __nv_bfloat16* Vd = buf + 64 * SROW;
        const int mc0 = c * 64;
        #pragma unroll
        for (int i = 0; i < 4; i++) {
            int l = tid + i * 128;
            int row = l >> 3, seg = (l & 7) * 8;
            cpa16((uint32_t)__cvta_generic_to_shared(&Kd[row * SROW + seg]),
                  &sksb[(mc0 + row) * 64 + seg]);
            cpa16((uint32_t)__cvta_generic_to_shared(&Vd[row * SROW + seg]),
                  &stvb[row * 512 + mc0 + seg]);
        }
        asm volatile("cp.async.commit_group;");
    };

    // Persistent Q fragments (both 16-row tiles); scale 0.125*log2(e) folded.
    const float qs = 0.125f * 1.4426950408889634f;
    uint32_t Qa[4][8];
    #pragma unroll
    for (int tt = 0; tt < 2; tt++) {
        const float* q0 = Qb + (size_t)(wrow + tt * 16 + g) * DIM;
        const float* q1 = Qb + (size_t)(wrow + tt * 16 + g + 8) * DIM;
        #pragma unroll
        for (int kk = 0; kk < 4; kk++) {
            float2 x0 = *(const float2*)&q0[kk * 16 + 2 * t4];
            float2 x1 = *(const float2*)&q1[kk * 16 + 2 * t4];
            float2 x2 = *(const float2*)&q0[kk * 16 + 2 * t4 + 8];
            float2 x3 = *(const float2*)&q1[kk * 16 + 2 * t4 + 8];
            Qa[kk][tt * 4 + 0] = pack_bf2(x0.x * qs, x0.y * qs);
            Qa[kk][tt * 4 + 1] = pack_bf2(x1.x * qs, x1.y * qs);
            Qa[kk][tt * 4 + 2] = pack_bf2(x2.x * qs, x2.y * qs);
            Qa[kk][tt * 4 + 3] = pack_bf2(x3.x * qs, x3.y * qs);
        }
    }

    float O0[8][4], O1[8][4];
    #pragma unroll
    for (int j = 0; j < 8; j++)
        #pragma unroll
        for (int c = 0; c < 4; c++) { O0[j][c] = 0.f; O1[j][c] = 0.f; }
    float sum0 = 0.f, sum1 = 0.f, sum2 = 0.f, sum3 = 0.f;

    stage(0, kvbuf);    // prologue: chunk 0 -> buffer 0

    for (int c = 0; c < 8; c++) {
        __nv_bfloat16* Ks = kvbuf + (c & 1) * KVSZ;
        __nv_bfloat16* Vs = Ks + 64 * SROW;

        if (c + 1 < 8) {
            stage(c + 1, kvbuf + ((c + 1) & 1) * KVSZ);
            asm volatile("cp.async.wait_group 1;");
        } else {
            asm volatile("cp.async.wait_group 0;");
        }
        __syncthreads();   // chunk-c tiles visible to all warps

        const __nv_bfloat16* KsW = Ks + g * SROW + 4 * t4;   // hoisted frag bases
        const __nv_bfloat16* VsW = Vs + g * SROW + 4 * t4;

        #pragma unroll
        for (int jj = 0; jj < 4; jj++) {
            // ---- GEMM1: logits for j-pair (2jj, 2jj+1), both 16-row tiles ----
            float Sa[4] = {0,0,0,0}, Sb[4] = {0,0,0,0};   // tile0/tile1, col j0
            float Sc[4] = {0,0,0,0}, Sd[4] = {0,0,0,0};   // tile0/tile1, col j1
            #pragma unroll
            for (int kk = 0; kk < 4; kk++) {
                uint2 Bx = *(const uint2*)&KsW[(2 * jj    ) * 8 * SROW + kk * 16];
                uint2 By = *(const uint2*)&KsW[(2 * jj + 1) * 8 * SROW + kk * 16];
                mma_bf16(Sa, Qa[kk][0], Qa[kk][1], Qa[kk][2], Qa[kk][3], Bx.x, Bx.y);
                mma_bf16(Sb, Qa[kk][4], Qa[kk][5], Qa[kk][6], Qa[kk][7], Bx.x, Bx.y);
                mma_bf16(Sc, Qa[kk][0], Qa[kk][1], Qa[kk][2], Qa[kk][3], By.x, By.y);
                mma_bf16(Sd, Qa[kk][4], Qa[kk][5], Qa[kk][6], Qa[kk][7], By.x, By.y);
            }
            // ---- exp + pack: C-frag (j0,j1) == A-frag of GEMM2 k-group jj ----
            float pa0 = ex2(Sa[0]), pa1 = ex2(Sa[1]), pa2 = ex2(Sa[2]), pa3 = ex2(Sa[3]);
            float pb0 = ex2(Sb[0]), pb1 = ex2(Sb[1]), pb2 = ex2(Sb[2]), pb3 = ex2(Sb[3]);
            float pc0 = ex2(Sc[0]), pc1 = ex2(Sc[1]), pc2 = ex2(Sc[2]), pc3 = ex2(Sc[3]);
            float pd0 = ex2(Sd[0]), pd1 = ex2(Sd[1]), pd2 = ex2(Sd[2]), pd3 = ex2(Sd[3]);
            sum0 += pa0 + pa1 + pc0 + pc1;     // tile0 row g
            sum1 += pa2 + pa3 + pc2 + pc3;     // tile0 row g+8
            sum2 += pb0 + pb1 + pd0 + pd1;     // tile1 row g
            sum3 += pb2 + pb3 + pd2 + pd3;     // tile1 row g+8
            uint32_t a0 = pack_bf2(pa0, pa1), a1 = pack_bf2(pa2, pa3);
            uint32_t a2 = pack_bf2(pc0, pc1), a3 = pack_bf2(pc2, pc3);
            uint32_t a4 = pack_bf2(pb0, pb1), a5 = pack_bf2(pb2, pb3);
            uint32_t a6 = pack_bf2(pd0, pd1), a7 = pack_bf2(pd2, pd3);
            // ---- GEMM2 partial: O += P(:, kk=jj) @ STV(kk=jj, :) ----
            #pragma unroll
            for (int j = 0; j < 8; j++) {
                uint2 Bv = *(const uint2*)&VsW[j * 8 * SROW + jj * 16];
                mma_bf16(O0[j], a0, a1, a2, a3, Bv.x, Bv.y);
                mma_bf16(O1[j], a4, a5, a6, a7, Bv.x, Bv.y);
            }
        }
        __syncthreads();   // all warps done reading chunk-c tiles
    }

    // quad-reduce row sums (lanes 4g..4g+3 share rows)
    sum0 += __shfl_xor_sync(0xffffffffu, sum0, 1);
    sum0 += __shfl_xor_sync(0xffffffffu, sum0, 2);
    sum1 += __shfl_xor_sync(0xffffffffu, sum1, 1);
    sum1 += __shfl_xor_sync(0xffffffffu, sum1, 2);
    sum2 += __shfl_xor_sync(0xffffffffu, sum2, 1);
    sum2 += __shfl_xor_sync(0xffffffffu, sum2, 2);
    sum3 += __shfl_xor_sync(0xffffffffu, sum3, 1);
    sum3 += __shfl_xor_sync(0xffffffffu, sum3, 2);
    const float i0 = 1.f / sum0, i1 = 1.f / sum1, i2 = 1.f / sum2, i3 = 1.f / sum3;

    const float* Vb = V + (size_t)bh * SEQ * DIM;
    float* Ob = Out + (size_t)bh * SEQ * DIM;
    const size_t r0 = wrow + g, r1 = r0 + 8, r2 = r0 + 16, r3 = r0 + 24;
    #pragma unroll
    for (int j = 0; j < 8; j++) {
        int cix = j * 8 + 2 * t4;
        float2 v0 = *(const float2*)&Vb[r0 * DIM + cix];
        float2 v1 = *(const float2*)&Vb[r1 * DIM + cix];
        float2 v2 = *(const float2*)&Vb[r2 * DIM + cix];
        float2 v3 = *(const float2*)&Vb[r3 * DIM + cix];
        *(float2*)&Ob[r0 * DIM + cix] = make_float2(O0[j][0] * i0 + v0.x, O0[j][1] * i0 + v0.y);
        *(float2*)&Ob[r1 * DIM + cix] = make_float2(O0[j][2] * i1 + v1.x, O0[j][3] * i1 + v1.y);
        *(float2*)&Ob[r2 * DIM + cix] = make_float2(O1[j][0] * i2 + v2.x, O1[j][1] * i2 + v2.y);
        *(float2*)&Ob[r3 * DIM + cix] = make_float2(O1[j][2] * i3 + v3.x, O1[j][3] * i3 + v3.y);
    }
}

extern "C" void kernel_launch(void* const* d_in, const int* in_sizes, int n_in,
                              void* d_out, int out_size) {
    const float* Q = (const float*)d_in[0];
    const float* K = (const float*)d_in[1];
    const float* V = (const float*)d_in[2];
    float*       O = (float*)d_out;

    const int smem = 2 * KVSZ * (int)sizeof(__nv_bfloat16);   // 40960 B
    cudaFuncSetAttribute(attn_kernel, cudaFuncAttributeMaxDynamicSharedMemorySize, smem);

    sketch_kernel<<<dim3(B_H, 8), 256>>>(K, V);
    attn_kernel<<<dim3(SEQ / 128, B_H), 128, smem>>>(Q, V, O);
}